// round 9
// baseline (speedup 1.0000x reference)
#include <cuda_runtime.h>
#include <cuda_fp16.h>
#include <math.h>
#include <stdint.h>

// ---------------- constants ----------------
#define B_ROWS   16384
#define D_DIM    1024
#define KDIM     1024           // fp16 K
#define KU       512            // uints per fp16 row
#define NCAT     3584           // 1024(Wc1)+1024(Wr1)+1024(Wa)+512(Wo1)
#define ORD_H    512
#define N_EXP    7
#define MAX_TILES 136
#define MAX_SLOTS (MAX_TILES*128)
#define KITERS   32             // KDIM / 32

// ---------------- scratch (float units) ----------------
#define OFF_HB    0LL                      // HB fp16 [16384][3584]
#define OFF_X2    29360128LL               // X fp16 [16384][1024]
#define OFF_DFC   37748736LL               // Dfc fp16 [17408][1024]
#define OFF_H12   46661632LL               // H1 fp16 [17408][1024]
#define OFF_H2    55574528LL               // H2 fp16 [17408][1024]
#define OFF_WCAT  64487424LL               // Wcat fp16 [3584][1024]
#define OFF_WE1   66322432LL               // We1 fp16 [7][1024][1024]
#define OFF_WE2   69992448LL
#define OFF_BCAT  73662464LL               // bcat fp32 [3584]
#define TOTAL_F   73666048LL

__device__ __align__(1024) float g_buf[TOTAL_F];

__device__ int d_size_idx[B_ROWS];
__device__ int d_perm[MAX_SLOTS];
__device__ int d_tile_expert[MAX_TILES];
__device__ int d_count[N_EXP];
__device__ int d_cursor[N_EXP];
__device__ int d_off[N_EXP];
__device__ int d_fix_count;
__device__ int d_fix_rows[B_ROWS];

// ---------------- baseline-PTX helpers ----------------
__device__ __forceinline__ uint32_t smem_to_u32(const void* p) {
    uint32_t a;
    asm("{ .reg .u64 t; cvta.to.shared.u64 t, %1; cvt.u32.u64 %0, t; }" : "=r"(a) : "l"(p));
    return a;
}
#define CP_ASYNC16(dst, src) \
    asm volatile("cp.async.cg.shared.global [%0], [%1], 16;" :: "r"(dst), "l"(src))
#define CP_COMMIT() asm volatile("cp.async.commit_group;" ::: "memory")
#define CP_WAIT2()  asm volatile("cp.async.wait_group 2;" ::: "memory")

#define LDSM_X4(r0, r1, r2, r3, addr) \
    asm volatile("ldmatrix.sync.aligned.m8n8.x4.shared.b16 {%0,%1,%2,%3}, [%4];" \
        : "=r"(r0), "=r"(r1), "=r"(r2), "=r"(r3) : "r"(addr))

#define MMA_F16(d, a, b) \
    asm volatile("mma.sync.aligned.m16n8k16.row.col.f32.f16.f16.f32 " \
        "{%0,%1,%2,%3}, {%4,%5,%6,%7}, {%8,%9}, {%0,%1,%2,%3};" \
        : "+f"((d)[0]), "+f"((d)[1]), "+f"((d)[2]), "+f"((d)[3]) \
        : "r"((a)[0]), "r"((a)[1]), "r"((a)[2]), "r"((a)[3]), "r"((b)[0]), "r"((b)[1]))

// pack two fp32 into one uint of 2 fp16
__device__ __forceinline__ unsigned pack2(float a, float b) {
    const unsigned ha = (unsigned)__half_as_ushort(__float2half_rn(a));
    const unsigned hb = (unsigned)__half_as_ushort(__float2half_rn(b));
    return ha | (hb << 16);
}

// ---------------- conversions ----------------
__global__ void conv_f2h_kernel(const float* __restrict__ in, uint2* __restrict__ out)
{
    const size_t i = (size_t)blockIdx.x * 256 + threadIdx.x;   // float4 index
    const float4 v = reinterpret_cast<const float4*>(in)[i];
    out[i] = make_uint2(pack2(v.x, v.y), pack2(v.z, v.w));
}

// W [K,N] fp32 -> out [N][K] fp16 (transpose); grid.z = expert
__global__ void conv_w_kernel(const float* __restrict__ W, unsigned* __restrict__ out,
                              int K, int N)
{
    __shared__ float t[64][33];
    const int k0 = blockIdx.x * 64, n0 = blockIdx.y * 32;
    W   += (size_t)blockIdx.z * K * N;
    out += (size_t)blockIdx.z * N * (K / 2);
    for (int r = threadIdx.y; r < 64; r += 8)
        t[r][threadIdx.x] = W[(size_t)(k0 + r) * N + n0 + threadIdx.x];
    __syncthreads();
    for (int r = threadIdx.y; r < 32; r += 8)
        out[(size_t)(n0 + r) * (K / 2) + k0 / 2 + threadIdx.x] =
            pack2(t[2 * threadIdx.x][r], t[2 * threadIdx.x + 1][r]);
}

// fused conversion of all four stage-1 weights into Wcat [3584][1024] fp16
__global__ void conv_wcat_kernel(const float* __restrict__ Wc1, const float* __restrict__ Wr1,
                                 const float* __restrict__ Wa, const float* __restrict__ Wo1,
                                 unsigned* __restrict__ out)
{
    __shared__ float t[64][33];
    const int k0 = blockIdx.x * 64;
    const int nc0 = blockIdx.y * 32;
    const float* W; int N; int nl;
    if (nc0 < 1024)      { W = Wc1; N = 1024; nl = nc0; }
    else if (nc0 < 2048) { W = Wr1; N = 1024; nl = nc0 - 1024; }
    else if (nc0 < 3072) { W = Wa;  N = 1024; nl = nc0 - 2048; }
    else                 { W = Wo1; N = 512;  nl = nc0 - 3072; }
    for (int r = threadIdx.y; r < 64; r += 8)
        t[r][threadIdx.x] = W[(size_t)(k0 + r) * N + nl + threadIdx.x];
    __syncthreads();
    for (int r = threadIdx.y; r < 32; r += 8)
        out[(size_t)(nc0 + r) * KU + k0 / 2 + threadIdx.x] =
            pack2(t[2 * threadIdx.x][r], t[2 * threadIdx.x + 1][r]);
}

__global__ void bias_cat_kernel(const float* bc1, const float* br1,
                                const float* ba, const float* bo1, float* bcat)
{
    const int i = blockIdx.x * 256 + threadIdx.x;
    if (i < 1024)      bcat[i] = bc1[i];
    else if (i < 2048) bcat[i] = br1[i - 1024];
    else if (i < 3072) bcat[i] = ba[i - 2048];
    else if (i < 3584) bcat[i] = bo1[i - 3072];
}

// combined routing init: perm, counts, tile map, fix counter
__global__ void init_kernel()
{
    const int i = blockIdx.x * blockDim.x + threadIdx.x;
    if (i < MAX_SLOTS) d_perm[i] = -1;
    if (i < N_EXP) { d_count[i] = 0; d_cursor[i] = 0; d_off[i] = 0; }
    if (i < MAX_TILES) d_tile_expert[i] = -1;
    if (i == 0) d_fix_count = 0;
}

// gather Df fp16 rows (HB half-cols 2048..3071) through perm -> compact fp16 rows
__global__ void gather_kernel(const __half* __restrict__ HBh, uint4* __restrict__ out)
{
    const int slot = blockIdx.x;
    const int p = d_perm[slot];
    uint4 o = make_uint4(0u, 0u, 0u, 0u);
    if (p >= 0)
        o = reinterpret_cast<const uint4*>(HBh + (size_t)p * NCAT + 2048)[threadIdx.x];
    out[(size_t)slot * 128 + threadIdx.x] = o;
}

// ---------------- HMMA GEMM: C = relu(A @ W^T + bias), fp16 in / fp32 acc ----------------
// 256 threads / 8 warps, CTA tile 128x256, warp tile 64x64 (2 wm x 4 wn),
// BK=32, 4-stage cp.async. outHalf: 0 -> fp32 C, 1 -> fp16-packed C.
#define STAGE_B   30720                // A 128*80 + B 256*80
#define GSMEM_SZ  (STAGE_B * 4)        // 122880

__global__ __launch_bounds__(256, 1)
void gemm_hmma(const __half* __restrict__ A,
               const __half* __restrict__ Bw,
               const float* __restrict__ biasBase,
               void* __restrict__ Cv, int ldc,
               int useExpert, long long wStride, int biasStride, int outHalf)
{
    extern __shared__ __align__(128) unsigned char smem[];
    const int tileN = blockIdx.x, tileM = blockIdx.y;
    int e = 0;
    if (useExpert) { e = d_tile_expert[tileM]; if (e < 0) return; }

    const __half* Ap = A + (size_t)tileM * 128 * KDIM;
    const __half* Bp = Bw + (size_t)e * wStride + (size_t)tileN * 256 * KDIM;
    const float* bias = biasBase + (size_t)e * biasStride;

    const uint32_t sbase = smem_to_u32(smem);
    const int tid = threadIdx.x, wid = tid >> 5, lane = tid & 31;
    const int wm = wid >> 2, wn = wid & 3;          // 2 x 4 warp grid
    const int lrow = lane & 15, lcol = lane >> 4;

    const int rr = tid >> 2, ss = tid & 3;          // cp.async mapping

    auto issue = [&](int kt) {
        const uint32_t base = sbase + (kt & 3) * STAGE_B;
        const int k0 = kt * 32;
        // A: 128 rows
        CP_ASYNC16(base + rr * 80 + ss * 16,
                   Ap + (size_t)rr * KDIM + k0 + ss * 8);
        CP_ASYNC16(base + (rr + 64) * 80 + ss * 16,
                   Ap + (size_t)(rr + 64) * KDIM + k0 + ss * 8);
        // B: 256 rows
        #pragma unroll
        for (int q = 0; q < 4; q++)
            CP_ASYNC16(base + 10240 + (rr + q * 64) * 80 + ss * 16,
                       Bp + (size_t)(rr + q * 64) * KDIM + k0 + ss * 8);
    };

    float acc[4][8][4] = {};

    issue(0); CP_COMMIT();
    issue(1); CP_COMMIT();
    issue(2); CP_COMMIT();

    for (int kt = 0; kt < KITERS; kt++) {
        CP_WAIT2();
        __syncthreads();
        if (kt + 3 < KITERS) issue(kt + 3);
        CP_COMMIT();

        const uint32_t ab = sbase + (kt & 3) * STAGE_B;
        const uint32_t bb = ab + 10240;
        #pragma unroll
        for (int kk = 0; kk < 2; kk++) {
            uint32_t a[4][4];
            #pragma unroll
            for (int i = 0; i < 4; i++) {
                const uint32_t addr = ab + (wm * 64 + i * 16 + lrow) * 80 + (kk * 16 + lcol * 8) * 2;
                LDSM_X4(a[i][0], a[i][1], a[i][2], a[i][3], addr);
            }
            uint32_t b[8][2];
            #pragma unroll
            for (int j4 = 0; j4 < 4; j4++) {
                uint32_t q0, q1, q2, q3;
                const uint32_t addr = bb + (wn * 64 + j4 * 16 + lrow) * 80 + (kk * 16 + lcol * 8) * 2;
                LDSM_X4(q0, q1, q2, q3, addr);
                b[2 * j4][0] = q0;     b[2 * j4][1] = q2;
                b[2 * j4 + 1][0] = q1; b[2 * j4 + 1][1] = q3;
            }
            #pragma unroll
            for (int i = 0; i < 4; i++)
                #pragma unroll
                for (int j = 0; j < 8; j++)
                    MMA_F16(acc[i][j], a[i], b[j]);
        }
    }

    // epilogue: bias + relu
    const int rbase = tileM * 128 + wm * 64 + (lane >> 2);
    const int cbase = tileN * 256 + wn * 64 + (lane & 3) * 2;
    if (outHalf) {
        unsigned* C16 = (unsigned*)Cv;
        const int ldu = ldc >> 1;
        #pragma unroll
        for (int j = 0; j < 8; j++) {
            const int col = cbase + j * 8;
            const float2 bz = *reinterpret_cast<const float2*>(bias + col);
            #pragma unroll
            for (int i = 0; i < 4; i++) {
                const int ra = rbase + i * 16;
                C16[(size_t)ra * ldu + (col >> 1)] =
                    pack2(fmaxf(acc[i][j][0] + bz.x, 0.f), fmaxf(acc[i][j][1] + bz.y, 0.f));
                C16[(size_t)(ra + 8) * ldu + (col >> 1)] =
                    pack2(fmaxf(acc[i][j][2] + bz.x, 0.f), fmaxf(acc[i][j][3] + bz.y, 0.f));
            }
        }
    } else {
        float* C = (float*)Cv;
        #pragma unroll
        for (int j = 0; j < 8; j++) {
            const int col = cbase + j * 8;
            const float2 bz = *reinterpret_cast<const float2*>(bias + col);
            #pragma unroll
            for (int i = 0; i < 4; i++) {
                const int ra = rbase + i * 16;
                float2 v0, v1;
                v0.x = fmaxf(acc[i][j][0] + bz.x, 0.f);
                v0.y = fmaxf(acc[i][j][1] + bz.y, 0.f);
                v1.x = fmaxf(acc[i][j][2] + bz.x, 0.f);
                v1.y = fmaxf(acc[i][j][3] + bz.y, 0.f);
                *reinterpret_cast<float2*>(C + (size_t)ra * ldc + col) = v0;
                *reinterpret_cast<float2*>(C + (size_t)(ra + 8) * ldc + col) = v1;
            }
        }
    }
}

// ---------------- fused head (fp16 inputs) + expert count ----------------
__global__ void head_kernel(const __half* __restrict__ HBh,
                            const float* __restrict__ Wc2, const float* __restrict__ bc2,
                            const float* __restrict__ Wo2, const float* __restrict__ bo2,
                            const float* __restrict__ Wr2, const float* __restrict__ br2,
                            float* __restrict__ out)
{
    const int row = blockIdx.x * blockDim.y + threadIdx.y;
    if (row >= B_ROWS) return;
    const int lane = threadIdx.x;
    const __half2* h2 = reinterpret_cast<const __half2*>(HBh + (size_t)row * NCAT);

    float a[7] = {0,0,0,0,0,0,0};
    for (int k2 = lane; k2 < 512; k2 += 32) {
        const float2 hv = __half22float2(h2[k2]);
        const float* w = Wc2 + (2 * k2) * 7;
        #pragma unroll
        for (int c = 0; c < 7; c++) a[c] += hv.x * w[c] + hv.y * w[7 + c];
    }
    float o[6] = {0,0,0,0,0,0};
    for (int k2 = lane; k2 < 256; k2 += 32) {
        const float2 hv = __half22float2(h2[1536 + k2]);
        const float* w = Wo2 + (2 * k2) * 6;
        #pragma unroll
        for (int c = 0; c < 6; c++) o[c] += hv.x * w[c] + hv.y * w[6 + c];
    }
    float r = 0.f;
    for (int k2 = lane; k2 < 512; k2 += 32) {
        const float2 hv = __half22float2(h2[512 + k2]);
        r += hv.x * Wr2[2 * k2] + hv.y * Wr2[2 * k2 + 1];
    }

    #pragma unroll
    for (int off = 16; off; off >>= 1) {
        #pragma unroll
        for (int c = 0; c < 7; c++) a[c] += __shfl_xor_sync(0xffffffffu, a[c], off);
        #pragma unroll
        for (int c = 0; c < 6; c++) o[c] += __shfl_xor_sync(0xffffffffu, o[c], off);
        r += __shfl_xor_sync(0xffffffffu, r, off);
    }
    if (lane == 0) {
        float sl[7];
        #pragma unroll
        for (int c = 0; c < 7; c++) sl[c] = a[c] + bc2[c];
        float mx = sl[0];
        #pragma unroll
        for (int c = 1; c < 7; c++) mx = fmaxf(mx, sl[c]);
        float ex[7], s = 0.f;
        #pragma unroll
        for (int c = 0; c < 7; c++) { ex[c] = expf(sl[c] - mx); s += ex[c]; }
        const float inv = 1.f / s;

        float expected = 0.f;
        int idx = 0; float best = sl[0], best2 = -1e30f;
        float* orow = out + (size_t)row * 24;
        #pragma unroll
        for (int c = 0; c < 7; c++) {
            const float p = ex[c] * inv;
            expected = fmaf(p, (float)c * (1.0f / 6.0f), expected);
            orow[c] = sl[c];
            orow[14 + c] = p;
            if (c > 0) {
                if (sl[c] > best) { best2 = best; best = sl[c]; idx = c; }
                else if (sl[c] > best2) best2 = sl[c];
            }
        }
        #pragma unroll
        for (int c = 0; c < 6; c++) orow[7 + c] = o[c] + bo2[c];
        const float resid = 0.35f * tanhf(r + br2[0]);
        orow[13] = fminf(fmaxf(expected + resid, 0.f), 1.f);
        d_size_idx[row] = idx;
        atomicAdd(&d_count[idx], 1);                 // fused count
        if (best - best2 < 4e-3f) {
            int p = atomicAdd(&d_fix_count, 1);
            if (p < B_ROWS) d_fix_rows[p] = row;
        }
    }
}

// exact fp32 argmax recompute for near-tie rows (adjusts counts on flips)
__global__ void fix_kernel(const float* __restrict__ x,
                           const float* __restrict__ Wc1, const float* __restrict__ bc1,
                           const float* __restrict__ Wc2, const float* __restrict__ bc2)
{
    __shared__ float xr[D_DIM];
    __shared__ float h[D_DIM];
    __shared__ float lg[8];
    int n = d_fix_count; if (n > B_ROWS) n = B_ROWS;
    for (int i = blockIdx.x; i < n; i += gridDim.x) {
        const int row = d_fix_rows[i];
        for (int k = threadIdx.x; k < D_DIM; k += 256) xr[k] = x[(size_t)row * D_DIM + k];
        __syncthreads();
        for (int j = threadIdx.x; j < D_DIM; j += 256) {
            float s = bc1[j];
            for (int k = 0; k < D_DIM; k++) s = fmaf(xr[k], Wc1[(size_t)k * D_DIM + j], s);
            h[j] = fmaxf(s, 0.f);
        }
        __syncthreads();
        const int w = threadIdx.x >> 5, l = threadIdx.x & 31;
        if (w < 7) {
            float s = 0.f;
            for (int k = l; k < D_DIM; k += 32) s = fmaf(h[k], Wc2[k * 7 + w], s);
            #pragma unroll
            for (int off = 16; off; off >>= 1) s += __shfl_xor_sync(0xffffffffu, s, off);
            if (!l) lg[w] = s + bc2[w];
        }
        __syncthreads();
        if (threadIdx.x == 0) {
            int idx = 0; float best = lg[0];
            #pragma unroll
            for (int c = 1; c < 7; c++) if (lg[c] > best) { best = lg[c]; idx = c; }
            const int old = d_size_idx[row];
            if (idx != old) {
                atomicSub(&d_count[old], 1);
                atomicAdd(&d_count[idx], 1);
                d_size_idx[row] = idx;
            }
        }
        __syncthreads();
    }
}

// ---------------- routing scan + scatter ----------------
__global__ void scan_kernel()
{
    int off = 0;
    for (int e = 0; e < N_EXP; e++) {
        d_off[e] = off;
        const int tiles = (d_count[e] + 127) >> 7;
        const int base = off >> 7;
        for (int t = 0; t < tiles; t++) d_tile_expert[base + t] = e;
        off += tiles << 7;
    }
}
__global__ void scatter_kernel()
{
    const int r = blockIdx.x * blockDim.x + threadIdx.x;
    if (r < B_ROWS) {
        const int e = d_size_idx[r];
        const int pos = d_off[e] + atomicAdd(&d_cursor[e], 1);
        d_perm[pos] = r;
    }
}

// ---------------- depth final projection (fp16 input) ----------------
__global__ void depth_final_kernel(const __half* __restrict__ H2h,
                                   const float* __restrict__ We3,
                                   const float* __restrict__ be3,
                                   float* __restrict__ out)
{
    const int slot = blockIdx.x * blockDim.y + threadIdx.y;
    if (slot >= MAX_SLOTS) return;
    const int e = d_tile_expert[slot >> 7];
    if (e < 0) return;
    const int p = d_perm[slot];
    if (p < 0) return;
    const int lane = threadIdx.x;
    float a0 = 0.f, a1 = 0.f, a2 = 0.f;
    const __half2* h2 = reinterpret_cast<const __half2*>(H2h + (size_t)slot * D_DIM);
    const float* w = We3 + (size_t)e * D_DIM * 3;
    for (int k2 = lane; k2 < 512; k2 += 32) {
        const float2 hv = __half22float2(h2[k2]);
        const int k = 2 * k2;
        a0 += hv.x * w[k * 3 + 0] + hv.y * w[k * 3 + 3];
        a1 += hv.x * w[k * 3 + 1] + hv.y * w[k * 3 + 4];
        a2 += hv.x * w[k * 3 + 2] + hv.y * w[k * 3 + 5];
    }
    #pragma unroll
    for (int off = 16; off; off >>= 1) {
        a0 += __shfl_xor_sync(0xffffffffu, a0, off);
        a1 += __shfl_xor_sync(0xffffffffu, a1, off);
        a2 += __shfl_xor_sync(0xffffffffu, a2, off);
    }
    if (lane == 0) {
        float* orow = out + (size_t)p * 24;
        orow[21] = a0 + be3[e * 3 + 0];
        orow[22] = a1 + be3[e * 3 + 1];
        orow[23] = a2 + be3[e * 3 + 2];
    }
}

// ---------------- launch ----------------
extern "C" void kernel_launch(void* const* d_in, const int* in_sizes, int n_in,
                              void* d_out, int out_size)
{
    const float* x   = (const float*)d_in[0];
    const float* Wc1 = (const float*)d_in[1];
    const float* bc1 = (const float*)d_in[2];
    const float* Wc2 = (const float*)d_in[3];
    const float* bc2 = (const float*)d_in[4];
    const float* Wo1 = (const float*)d_in[5];
    const float* bo1 = (const float*)d_in[6];
    const float* Wo2 = (const float*)d_in[7];
    const float* bo2 = (const float*)d_in[8];
    const float* Wr1 = (const float*)d_in[9];
    const float* br1 = (const float*)d_in[10];
    const float* Wr2 = (const float*)d_in[11];
    const float* br2 = (const float*)d_in[12];
    const float* Wa  = (const float*)d_in[13];
    const float* ba  = (const float*)d_in[14];
    const float* We1 = (const float*)d_in[15];
    const float* be1 = (const float*)d_in[16];
    const float* We2 = (const float*)d_in[17];
    const float* be2 = (const float*)d_in[18];
    const float* We3 = (const float*)d_in[19];
    const float* be3 = (const float*)d_in[20];
    float* out = (float*)d_out;

    float* buf = nullptr;
    cudaGetSymbolAddress((void**)&buf, g_buf);
    __half*   HBh  = (__half*)(buf + OFF_HB);
    unsigned* X2   = (unsigned*)(buf + OFF_X2);
    unsigned* Dfc  = (unsigned*)(buf + OFF_DFC);
    unsigned* H12  = (unsigned*)(buf + OFF_H12);
    __half*   H2h  = (__half*)(buf + OFF_H2);
    unsigned* Wcat = (unsigned*)(buf + OFF_WCAT);
    unsigned* W2e1 = (unsigned*)(buf + OFF_WE1);
    unsigned* W2e2 = (unsigned*)(buf + OFF_WE2);
    float*    bcat = buf + OFF_BCAT;

    cudaFuncSetAttribute(gemm_hmma, cudaFuncAttributeMaxDynamicSharedMemorySize, GSMEM_SZ);

    // conversions (plain fp16)
    conv_f2h_kernel<<<B_ROWS, 256>>>(x, (uint2*)X2);
    conv_wcat_kernel<<<dim3(16, 112), dim3(32, 8)>>>(Wc1, Wr1, Wa, Wo1, Wcat);
    conv_w_kernel<<<dim3(16, 32, N_EXP), dim3(32, 8)>>>(We1, W2e1, D_DIM, D_DIM);
    conv_w_kernel<<<dim3(16, 32, N_EXP), dim3(32, 8)>>>(We2, W2e2, D_DIM, D_DIM);
    bias_cat_kernel<<<14, 256>>>(bc1, br1, ba, bo1, bcat);
    init_kernel<<<(MAX_SLOTS + 255) / 256, 256>>>();

    // fused stage-1 GEMM: HB(fp16) = relu(X @ Wcat^T + bcat)   [tile 128x256]
    gemm_hmma<<<dim3(NCAT / 256, B_ROWS / 128), 256, GSMEM_SZ>>>(
        (const __half*)X2, (const __half*)Wcat, bcat, HBh, NCAT, 0, 0, 0, 1);

    // heads (+count) + near-tie fp32 fixup (+count adjust) + routing tables
    head_kernel<<<B_ROWS / 8, dim3(32, 8)>>>(HBh, Wc2, bc2, Wo2, bo2, Wr2, br2, out);
    fix_kernel<<<64, 256>>>(x, Wc1, bc1, Wc2, bc2);
    scan_kernel<<<1, 1>>>();
    scatter_kernel<<<(B_ROWS + 255) / 256, 256>>>();

    // expert dispatch + routed expert MLP (one expert per row, fp16 throughout)
    gather_kernel<<<MAX_SLOTS, 128>>>(HBh, (uint4*)Dfc);
    gemm_hmma<<<dim3(4, MAX_TILES), 256, GSMEM_SZ>>>(
        (const __half*)Dfc, (const __half*)W2e1, be1, H12, D_DIM, 1,
        (long long)D_DIM * KDIM, D_DIM, 1);
    gemm_hmma<<<dim3(4, MAX_TILES), 256, GSMEM_SZ>>>(
        (const __half*)H12, (const __half*)W2e2, be2, H2h, D_DIM, 1,
        (long long)D_DIM * KDIM, D_DIM, 1);

    // final 1024x3 projection scattered into output rows
    depth_final_kernel<<<MAX_SLOTS / 8, dim3(32, 8)>>>(H2h, We3, be3, out);
}

// round 10
// speedup vs baseline: 1.0681x; 1.0681x over previous
#include <cuda_runtime.h>
#include <cuda_fp16.h>
#include <math.h>
#include <stdint.h>

// ---------------- constants ----------------
#define B_ROWS   16384
#define D_DIM    1024
#define KDIM     1024           // fp16 K
#define KU       512            // uints per fp16 row
#define NCAT     3584           // 1024(Wc1)+1024(Wr1)+1024(Wa)+512(Wo1)
#define ORD_H    512
#define N_EXP    7
#define MAX_TILES 136
#define MAX_SLOTS (MAX_TILES*128)
#define KITERS   32             // KDIM / 32
#define NSTAGE   5

// ---------------- scratch (float units) ----------------
#define OFF_HB    0LL                      // HB fp16 [16384][3584]
#define OFF_X2    29360128LL               // X fp16 [16384][1024]
#define OFF_DFC   37748736LL               // Dfc fp16 [17408][1024]
#define OFF_H12   46661632LL               // H1 fp16 [17408][1024]
#define OFF_H2    55574528LL               // H2 fp16 [17408][1024]
#define OFF_WCAT  64487424LL               // Wcat fp16 [3584][1024]
#define OFF_WE1   66322432LL               // We1 fp16 [7][1024][1024]
#define OFF_WE2   69992448LL
#define OFF_BCAT  73662464LL               // bcat fp32 [3584]
#define TOTAL_F   73666048LL

__device__ __align__(1024) float g_buf[TOTAL_F];

__device__ int d_size_idx[B_ROWS];
__device__ int d_perm[MAX_SLOTS];
__device__ int d_tile_expert[MAX_TILES];
__device__ int d_count[N_EXP];
__device__ int d_cursor[N_EXP];
__device__ int d_off[N_EXP];
__device__ int d_fix_count;
__device__ int d_fix_rows[B_ROWS];

// ---------------- baseline-PTX helpers ----------------
__device__ __forceinline__ uint32_t smem_to_u32(const void* p) {
    uint32_t a;
    asm("{ .reg .u64 t; cvta.to.shared.u64 t, %1; cvt.u32.u64 %0, t; }" : "=r"(a) : "l"(p));
    return a;
}
#define CP_ASYNC16(dst, src) \
    asm volatile("cp.async.cg.shared.global [%0], [%1], 16;" :: "r"(dst), "l"(src))
#define CP_COMMIT() asm volatile("cp.async.commit_group;" ::: "memory")
#define CP_WAIT3()  asm volatile("cp.async.wait_group 3;" ::: "memory")

#define LDSM_X4(r0, r1, r2, r3, addr) \
    asm volatile("ldmatrix.sync.aligned.m8n8.x4.shared.b16 {%0,%1,%2,%3}, [%4];" \
        : "=r"(r0), "=r"(r1), "=r"(r2), "=r"(r3) : "r"(addr))

#define MMA_F16(d, a, b) \
    asm volatile("mma.sync.aligned.m16n8k16.row.col.f32.f16.f16.f32 " \
        "{%0,%1,%2,%3}, {%4,%5,%6,%7}, {%8,%9}, {%0,%1,%2,%3};" \
        : "+f"((d)[0]), "+f"((d)[1]), "+f"((d)[2]), "+f"((d)[3]) \
        : "r"((a)[0]), "r"((a)[1]), "r"((a)[2]), "r"((a)[3]), "r"((b)[0]), "r"((b)[1]))

// pack two fp32 into one uint of 2 fp16
__device__ __forceinline__ unsigned pack2(float a, float b) {
    const unsigned ha = (unsigned)__half_as_ushort(__float2half_rn(a));
    const unsigned hb = (unsigned)__half_as_ushort(__float2half_rn(b));
    return ha | (hb << 16);
}

// ---------------- conversions ----------------
__global__ void conv_f2h_kernel(const float* __restrict__ in, uint2* __restrict__ out)
{
    const size_t i = (size_t)blockIdx.x * 256 + threadIdx.x;   // float4 index
    const float4 v = reinterpret_cast<const float4*>(in)[i];
    out[i] = make_uint2(pack2(v.x, v.y), pack2(v.z, v.w));
}

// W [K,N] fp32 -> out [N][K] fp16 (transpose); grid.z = expert
__global__ void conv_w_kernel(const float* __restrict__ W, unsigned* __restrict__ out,
                              int K, int N)
{
    __shared__ float t[64][33];
    const int k0 = blockIdx.x * 64, n0 = blockIdx.y * 32;
    W   += (size_t)blockIdx.z * K * N;
    out += (size_t)blockIdx.z * N * (K / 2);
    for (int r = threadIdx.y; r < 64; r += 8)
        t[r][threadIdx.x] = W[(size_t)(k0 + r) * N + n0 + threadIdx.x];
    __syncthreads();
    for (int r = threadIdx.y; r < 32; r += 8)
        out[(size_t)(n0 + r) * (K / 2) + k0 / 2 + threadIdx.x] =
            pack2(t[2 * threadIdx.x][r], t[2 * threadIdx.x + 1][r]);
}

// fused conversion of all four stage-1 weights into Wcat [3584][1024] fp16
__global__ void conv_wcat_kernel(const float* __restrict__ Wc1, const float* __restrict__ Wr1,
                                 const float* __restrict__ Wa, const float* __restrict__ Wo1,
                                 unsigned* __restrict__ out)
{
    __shared__ float t[64][33];
    const int k0 = blockIdx.x * 64;
    const int nc0 = blockIdx.y * 32;
    const float* W; int N; int nl;
    if (nc0 < 1024)      { W = Wc1; N = 1024; nl = nc0; }
    else if (nc0 < 2048) { W = Wr1; N = 1024; nl = nc0 - 1024; }
    else if (nc0 < 3072) { W = Wa;  N = 1024; nl = nc0 - 2048; }
    else                 { W = Wo1; N = 512;  nl = nc0 - 3072; }
    for (int r = threadIdx.y; r < 64; r += 8)
        t[r][threadIdx.x] = W[(size_t)(k0 + r) * N + nl + threadIdx.x];
    __syncthreads();
    for (int r = threadIdx.y; r < 32; r += 8)
        out[(size_t)(nc0 + r) * KU + k0 / 2 + threadIdx.x] =
            pack2(t[2 * threadIdx.x][r], t[2 * threadIdx.x + 1][r]);
}

__global__ void bias_cat_kernel(const float* bc1, const float* br1,
                                const float* ba, const float* bo1, float* bcat)
{
    const int i = blockIdx.x * 256 + threadIdx.x;
    if (i < 1024)      bcat[i] = bc1[i];
    else if (i < 2048) bcat[i] = br1[i - 1024];
    else if (i < 3072) bcat[i] = ba[i - 2048];
    else if (i < 3584) bcat[i] = bo1[i - 3072];
}

// combined routing init: perm, counts, tile map, fix counter
__global__ void init_kernel()
{
    const int i = blockIdx.x * blockDim.x + threadIdx.x;
    if (i < MAX_SLOTS) d_perm[i] = -1;
    if (i < N_EXP) { d_count[i] = 0; d_cursor[i] = 0; d_off[i] = 0; }
    if (i < MAX_TILES) d_tile_expert[i] = -1;
    if (i == 0) d_fix_count = 0;
}

// gather Df fp16 rows (HB half-cols 2048..3071) through perm -> compact fp16 rows
__global__ void gather_kernel(const __half* __restrict__ HBh, uint4* __restrict__ out)
{
    const int slot = blockIdx.x;
    const int p = d_perm[slot];
    uint4 o = make_uint4(0u, 0u, 0u, 0u);
    if (p >= 0)
        o = reinterpret_cast<const uint4*>(HBh + (size_t)p * NCAT + 2048)[threadIdx.x];
    out[(size_t)slot * 128 + threadIdx.x] = o;
}

// ---------------- HMMA GEMM: C = relu(A @ W^T + bias), fp16 in / fp32 acc ----------------
// 256 threads / 8 warps (warp 32x64), tile 128x128, BK=32, 5-stage cp.async ring
// outHalf: 0 -> fp32 C, 1 -> fp16-packed C (ldc in elements either way)
#define STAGE_B   20480
#define GSMEM_SZ  (STAGE_B * NSTAGE)      // 102400

__global__ __launch_bounds__(256, 2)
void gemm_hmma(const __half* __restrict__ A,
               const __half* __restrict__ Bw,
               const float* __restrict__ biasBase,
               void* __restrict__ Cv, int ldc,
               int useExpert, long long wStride, int biasStride, int outHalf)
{
    extern __shared__ __align__(128) unsigned char smem[];
    const int tileN = blockIdx.x, tileM = blockIdx.y;
    int e = 0;
    if (useExpert) { e = d_tile_expert[tileM]; if (e < 0) return; }

    const __half* Ap = A + (size_t)tileM * 128 * KDIM;
    const __half* Bp = Bw + (size_t)e * wStride + (size_t)tileN * 128 * KDIM;
    const float* bias = biasBase + (size_t)e * biasStride;

    const uint32_t sbase = smem_to_u32(smem);
    const int tid = threadIdx.x, wid = tid >> 5, lane = tid & 31;
    const int wm = wid >> 1, wn = wid & 1;
    const int lrow = lane & 15, lcol = lane >> 4;

    const int r0c = tid >> 2, s0c = tid & 3;
    const int r1c = 64 + (tid >> 2), s1c = tid & 3;

    auto issue = [&](int kt, int stage) {
        const uint32_t base = sbase + stage * STAGE_B;
        const int k0 = kt * 32;
        CP_ASYNC16(base + r0c * 80 + s0c * 16,         Ap + (size_t)r0c * KDIM + k0 + s0c * 8);
        CP_ASYNC16(base + r1c * 80 + s1c * 16,         Ap + (size_t)r1c * KDIM + k0 + s1c * 8);
        CP_ASYNC16(base + 10240 + r0c * 80 + s0c * 16, Bp + (size_t)r0c * KDIM + k0 + s0c * 8);
        CP_ASYNC16(base + 10240 + r1c * 80 + s1c * 16, Bp + (size_t)r1c * KDIM + k0 + s1c * 8);
    };

    float acc[2][8][4] = {};

    issue(0, 0); CP_COMMIT();
    issue(1, 1); CP_COMMIT();
    issue(2, 2); CP_COMMIT();
    issue(3, 3); CP_COMMIT();

    int sc = 0;        // consume stage for kt
    int si = 4;        // issue stage for kt+4
    for (int kt = 0; kt < KITERS; kt++) {
        CP_WAIT3();
        __syncthreads();
        if (kt + 4 < KITERS) issue(kt + 4, si);
        CP_COMMIT();

        const uint32_t ab = sbase + sc * STAGE_B;
        const uint32_t bb = ab + 10240;
        #pragma unroll
        for (int kk = 0; kk < 2; kk++) {
            uint32_t a[2][4];
            #pragma unroll
            for (int i = 0; i < 2; i++) {
                const uint32_t addr = ab + (wm * 32 + i * 16 + lrow) * 80 + (kk * 16 + lcol * 8) * 2;
                LDSM_X4(a[i][0], a[i][1], a[i][2], a[i][3], addr);
            }
            uint32_t b[8][2];
            #pragma unroll
            for (int j4 = 0; j4 < 4; j4++) {
                uint32_t q0, q1, q2, q3;
                const uint32_t addr = bb + (wn * 64 + j4 * 16 + lrow) * 80 + (kk * 16 + lcol * 8) * 2;
                LDSM_X4(q0, q1, q2, q3, addr);
                b[2 * j4][0] = q0;     b[2 * j4][1] = q2;
                b[2 * j4 + 1][0] = q1; b[2 * j4 + 1][1] = q3;
            }
            #pragma unroll
            for (int i = 0; i < 2; i++)
                #pragma unroll
                for (int j = 0; j < 8; j++)
                    MMA_F16(acc[i][j], a[i], b[j]);
        }
        sc = (sc + 1 == NSTAGE) ? 0 : sc + 1;
        si = (si + 1 == NSTAGE) ? 0 : si + 1;
    }

    // epilogue: bias + relu
    const int rbase = tileM * 128 + wm * 32 + (lane >> 2);
    const int cbase = tileN * 128 + wn * 64 + (lane & 3) * 2;
    if (outHalf) {
        unsigned* C16 = (unsigned*)Cv;
        const int ldu = ldc >> 1;
        #pragma unroll
        for (int j = 0; j < 8; j++) {
            const int col = cbase + j * 8;
            const float2 bz = *reinterpret_cast<const float2*>(bias + col);
            #pragma unroll
            for (int i = 0; i < 2; i++) {
                const int ra = rbase + i * 16;
                C16[(size_t)ra * ldu + (col >> 1)] =
                    pack2(fmaxf(acc[i][j][0] + bz.x, 0.f), fmaxf(acc[i][j][1] + bz.y, 0.f));
                C16[(size_t)(ra + 8) * ldu + (col >> 1)] =
                    pack2(fmaxf(acc[i][j][2] + bz.x, 0.f), fmaxf(acc[i][j][3] + bz.y, 0.f));
            }
        }
    } else {
        float* C = (float*)Cv;
        #pragma unroll
        for (int j = 0; j < 8; j++) {
            const int col = cbase + j * 8;
            const float2 bz = *reinterpret_cast<const float2*>(bias + col);
            #pragma unroll
            for (int i = 0; i < 2; i++) {
                const int ra = rbase + i * 16;
                float2 v0, v1;
                v0.x = fmaxf(acc[i][j][0] + bz.x, 0.f);
                v0.y = fmaxf(acc[i][j][1] + bz.y, 0.f);
                v1.x = fmaxf(acc[i][j][2] + bz.x, 0.f);
                v1.y = fmaxf(acc[i][j][3] + bz.y, 0.f);
                *reinterpret_cast<float2*>(C + (size_t)ra * ldc + col) = v0;
                *reinterpret_cast<float2*>(C + (size_t)(ra + 8) * ldc + col) = v1;
            }
        }
    }
}

// ---------------- fused head (fp16 inputs) + expert count ----------------
__global__ void head_kernel(const __half* __restrict__ HBh,
                            const float* __restrict__ Wc2, const float* __restrict__ bc2,
                            const float* __restrict__ Wo2, const float* __restrict__ bo2,
                            const float* __restrict__ Wr2, const float* __restrict__ br2,
                            float* __restrict__ out)
{
    const int row = blockIdx.x * blockDim.y + threadIdx.y;
    if (row >= B_ROWS) return;
    const int lane = threadIdx.x;
    const __half2* h2 = reinterpret_cast<const __half2*>(HBh + (size_t)row * NCAT);

    float a[7] = {0,0,0,0,0,0,0};
    for (int k2 = lane; k2 < 512; k2 += 32) {
        const float2 hv = __half22float2(h2[k2]);
        const float* w = Wc2 + (2 * k2) * 7;
        #pragma unroll
        for (int c = 0; c < 7; c++) a[c] += hv.x * w[c] + hv.y * w[7 + c];
    }
    float o[6] = {0,0,0,0,0,0};
    for (int k2 = lane; k2 < 256; k2 += 32) {
        const float2 hv = __half22float2(h2[1536 + k2]);
        const float* w = Wo2 + (2 * k2) * 6;
        #pragma unroll
        for (int c = 0; c < 6; c++) o[c] += hv.x * w[c] + hv.y * w[6 + c];
    }
    float r = 0.f;
    for (int k2 = lane; k2 < 512; k2 += 32) {
        const float2 hv = __half22float2(h2[512 + k2]);
        r += hv.x * Wr2[2 * k2] + hv.y * Wr2[2 * k2 + 1];
    }

    #pragma unroll
    for (int off = 16; off; off >>= 1) {
        #pragma unroll
        for (int c = 0; c < 7; c++) a[c] += __shfl_xor_sync(0xffffffffu, a[c], off);
        #pragma unroll
        for (int c = 0; c < 6; c++) o[c] += __shfl_xor_sync(0xffffffffu, o[c], off);
        r += __shfl_xor_sync(0xffffffffu, r, off);
    }
    if (lane == 0) {
        float sl[7];
        #pragma unroll
        for (int c = 0; c < 7; c++) sl[c] = a[c] + bc2[c];
        float mx = sl[0];
        #pragma unroll
        for (int c = 1; c < 7; c++) mx = fmaxf(mx, sl[c]);
        float ex[7], s = 0.f;
        #pragma unroll
        for (int c = 0; c < 7; c++) { ex[c] = expf(sl[c] - mx); s += ex[c]; }
        const float inv = 1.f / s;

        float expected = 0.f;
        int idx = 0; float best = sl[0], best2 = -1e30f;
        float* orow = out + (size_t)row * 24;
        #pragma unroll
        for (int c = 0; c < 7; c++) {
            const float p = ex[c] * inv;
            expected = fmaf(p, (float)c * (1.0f / 6.0f), expected);
            orow[c] = sl[c];
            orow[14 + c] = p;
            if (c > 0) {
                if (sl[c] > best) { best2 = best; best = sl[c]; idx = c; }
                else if (sl[c] > best2) best2 = sl[c];
            }
        }
        #pragma unroll
        for (int c = 0; c < 6; c++) orow[7 + c] = o[c] + bo2[c];
        const float resid = 0.35f * tanhf(r + br2[0]);
        orow[13] = fminf(fmaxf(expected + resid, 0.f), 1.f);
        d_size_idx[row] = idx;
        atomicAdd(&d_count[idx], 1);                 // fused count
        if (best - best2 < 4e-3f) {
            int p = atomicAdd(&d_fix_count, 1);
            if (p < B_ROWS) d_fix_rows[p] = row;
        }
    }
}

// exact fp32 argmax recompute for near-tie rows (adjusts counts on flips)
__global__ void fix_kernel(const float* __restrict__ x,
                           const float* __restrict__ Wc1, const float* __restrict__ bc1,
                           const float* __restrict__ Wc2, const float* __restrict__ bc2)
{
    __shared__ float xr[D_DIM];
    __shared__ float h[D_DIM];
    __shared__ float lg[8];
    int n = d_fix_count; if (n > B_ROWS) n = B_ROWS;
    for (int i = blockIdx.x; i < n; i += gridDim.x) {
        const int row = d_fix_rows[i];
        for (int k = threadIdx.x; k < D_DIM; k += 256) xr[k] = x[(size_t)row * D_DIM + k];
        __syncthreads();
        for (int j = threadIdx.x; j < D_DIM; j += 256) {
            float s = bc1[j];
            for (int k = 0; k < D_DIM; k++) s = fmaf(xr[k], Wc1[(size_t)k * D_DIM + j], s);
            h[j] = fmaxf(s, 0.f);
        }
        __syncthreads();
        const int w = threadIdx.x >> 5, l = threadIdx.x & 31;
        if (w < 7) {
            float s = 0.f;
            for (int k = l; k < D_DIM; k += 32) s = fmaf(h[k], Wc2[k * 7 + w], s);
            #pragma unroll
            for (int off = 16; off; off >>= 1) s += __shfl_xor_sync(0xffffffffu, s, off);
            if (!l) lg[w] = s + bc2[w];
        }
        __syncthreads();
        if (threadIdx.x == 0) {
            int idx = 0; float best = lg[0];
            #pragma unroll
            for (int c = 1; c < 7; c++) if (lg[c] > best) { best = lg[c]; idx = c; }
            const int old = d_size_idx[row];
            if (idx != old) {
                atomicSub(&d_count[old], 1);
                atomicAdd(&d_count[idx], 1);
                d_size_idx[row] = idx;
            }
        }
        __syncthreads();
    }
}

// ---------------- routing scan + scatter ----------------
__global__ void scan_kernel()
{
    int off = 0;
    for (int e = 0; e < N_EXP; e++) {
        d_off[e] = off;
        const int tiles = (d_count[e] + 127) >> 7;
        const int base = off >> 7;
        for (int t = 0; t < tiles; t++) d_tile_expert[base + t] = e;
        off += tiles << 7;
    }
}
__global__ void scatter_kernel()
{
    const int r = blockIdx.x * blockDim.x + threadIdx.x;
    if (r < B_ROWS) {
        const int e = d_size_idx[r];
        const int pos = d_off[e] + atomicAdd(&d_cursor[e], 1);
        d_perm[pos] = r;
    }
}

// ---------------- depth final projection (fp16 input) ----------------
__global__ void depth_final_kernel(const __half* __restrict__ H2h,
                                   const float* __restrict__ We3,
                                   const float* __restrict__ be3,
                                   float* __restrict__ out)
{
    const int slot = blockIdx.x * blockDim.y + threadIdx.y;
    if (slot >= MAX_SLOTS) return;
    const int e = d_tile_expert[slot >> 7];
    if (e < 0) return;
    const int p = d_perm[slot];
    if (p < 0) return;
    const int lane = threadIdx.x;
    float a0 = 0.f, a1 = 0.f, a2 = 0.f;
    const __half2* h2 = reinterpret_cast<const __half2*>(H2h + (size_t)slot * D_DIM);
    const float* w = We3 + (size_t)e * D_DIM * 3;
    for (int k2 = lane; k2 < 512; k2 += 32) {
        const float2 hv = __half22float2(h2[k2]);
        const int k = 2 * k2;
        a0 += hv.x * w[k * 3 + 0] + hv.y * w[k * 3 + 3];
        a1 += hv.x * w[k * 3 + 1] + hv.y * w[k * 3 + 4];
        a2 += hv.x * w[k * 3 + 2] + hv.y * w[k * 3 + 5];
    }
    #pragma unroll
    for (int off = 16; off; off >>= 1) {
        a0 += __shfl_xor_sync(0xffffffffu, a0, off);
        a1 += __shfl_xor_sync(0xffffffffu, a1, off);
        a2 += __shfl_xor_sync(0xffffffffu, a2, off);
    }
    if (lane == 0) {
        float* orow = out + (size_t)p * 24;
        orow[21] = a0 + be3[e * 3 + 0];
        orow[22] = a1 + be3[e * 3 + 1];
        orow[23] = a2 + be3[e * 3 + 2];
    }
}

// ---------------- launch ----------------
extern "C" void kernel_launch(void* const* d_in, const int* in_sizes, int n_in,
                              void* d_out, int out_size)
{
    const float* x   = (const float*)d_in[0];
    const float* Wc1 = (const float*)d_in[1];
    const float* bc1 = (const float*)d_in[2];
    const float* Wc2 = (const float*)d_in[3];
    const float* bc2 = (const float*)d_in[4];
    const float* Wo1 = (const float*)d_in[5];
    const float* bo1 = (const float*)d_in[6];
    const float* Wo2 = (const float*)d_in[7];
    const float* bo2 = (const float*)d_in[8];
    const float* Wr1 = (const float*)d_in[9];
    const float* br1 = (const float*)d_in[10];
    const float* Wr2 = (const float*)d_in[11];
    const float* br2 = (const float*)d_in[12];
    const float* Wa  = (const float*)d_in[13];
    const float* ba  = (const float*)d_in[14];
    const float* We1 = (const float*)d_in[15];
    const float* be1 = (const float*)d_in[16];
    const float* We2 = (const float*)d_in[17];
    const float* be2 = (const float*)d_in[18];
    const float* We3 = (const float*)d_in[19];
    const float* be3 = (const float*)d_in[20];
    float* out = (float*)d_out;

    float* buf = nullptr;
    cudaGetSymbolAddress((void**)&buf, g_buf);
    __half*   HBh  = (__half*)(buf + OFF_HB);
    unsigned* X2   = (unsigned*)(buf + OFF_X2);
    unsigned* Dfc  = (unsigned*)(buf + OFF_DFC);
    unsigned* H12  = (unsigned*)(buf + OFF_H12);
    __half*   H2h  = (__half*)(buf + OFF_H2);
    unsigned* Wcat = (unsigned*)(buf + OFF_WCAT);
    unsigned* W2e1 = (unsigned*)(buf + OFF_WE1);
    unsigned* W2e2 = (unsigned*)(buf + OFF_WE2);
    float*    bcat = buf + OFF_BCAT;

    cudaFuncSetAttribute(gemm_hmma, cudaFuncAttributeMaxDynamicSharedMemorySize, GSMEM_SZ);

    // conversions (plain fp16)
    conv_f2h_kernel<<<B_ROWS, 256>>>(x, (uint2*)X2);
    conv_wcat_kernel<<<dim3(16, 112), dim3(32, 8)>>>(Wc1, Wr1, Wa, Wo1, Wcat);
    conv_w_kernel<<<dim3(16, 32, N_EXP), dim3(32, 8)>>>(We1, W2e1, D_DIM, D_DIM);
    conv_w_kernel<<<dim3(16, 32, N_EXP), dim3(32, 8)>>>(We2, W2e2, D_DIM, D_DIM);
    bias_cat_kernel<<<14, 256>>>(bc1, br1, ba, bo1, bcat);
    init_kernel<<<(MAX_SLOTS + 255) / 256, 256>>>();

    // fused stage-1 GEMM: HB(fp16) = relu(X @ Wcat^T + bcat)
    gemm_hmma<<<dim3(NCAT / 128, B_ROWS / 128), 256, GSMEM_SZ>>>(
        (const __half*)X2, (const __half*)Wcat, bcat, HBh, NCAT, 0, 0, 0, 1);

    // heads (+count) + near-tie fp32 fixup (+count adjust) + routing tables
    head_kernel<<<B_ROWS / 8, dim3(32, 8)>>>(HBh, Wc2, bc2, Wo2, bo2, Wr2, br2, out);
    fix_kernel<<<64, 256>>>(x, Wc1, bc1, Wc2, bc2);
    scan_kernel<<<1, 1>>>();
    scatter_kernel<<<(B_ROWS + 255) / 256, 256>>>();

    // expert dispatch + routed expert MLP (one expert per row, fp16 throughout)
    gather_kernel<<<MAX_SLOTS, 128>>>(HBh, (uint4*)Dfc);
    gemm_hmma<<<dim3(8, MAX_TILES), 256, GSMEM_SZ>>>(
        (const __half*)Dfc, (const __half*)W2e1, be1, H12, D_DIM, 1,
        (long long)D_DIM * KDIM, D_DIM, 1);
    gemm_hmma<<<dim3(8, MAX_TILES), 256, GSMEM_SZ>>>(
        (const __half*)H12, (const __half*)W2e2, be2, H2h, D_DIM, 1,
        (long long)D_DIM * KDIM, D_DIM, 1);

    // final 1024x3 projection scattered into output rows
    depth_final_kernel<<<MAX_SLOTS / 8, dim3(32, 8)>>>(H2h, We3, be3, out);
}

// round 11
// speedup vs baseline: 1.0874x; 1.0181x over previous
#include <cuda_runtime.h>
#include <cuda_fp16.h>
#include <math.h>
#include <stdint.h>

// ---------------- constants ----------------
#define B_ROWS   16384
#define D_DIM    1024
#define KDIM     1024           // fp16 K
#define KU       512
#define NCAT     3584           // 1024(Wc1)+1024(Wr1)+1024(Wa)+512(Wo1)
#define ORD_H    512
#define N_EXP    7
#define MAX_TILES 136
#define MAX_SLOTS (MAX_TILES*128)
#define KITERS   32             // KDIM / 32
#define NSTAGE   5

// ---------------- scratch (float units) ----------------
#define OFF_HB    0LL                      // HB fp16 [16384][3584]
#define OFF_X2    29360128LL               // X fp16 [16384][1024]
#define OFF_H12   37748736LL               // H1 fp16 [17408][1024]
#define OFF_WCAT  46661632LL               // Wcat fp16 [3584][1024]
#define OFF_WE1   48496640LL               // We1 fp16 [7][1024][1024]
#define OFF_WE2   52166656LL
#define OFF_BCAT  55836672LL               // bcat fp32 [3584]
#define TOTAL_F   55840256LL

__device__ __align__(1024) float g_buf[TOTAL_F];

__device__ int d_size_idx[B_ROWS];
__device__ int d_perm[MAX_SLOTS];
__device__ int d_tile_expert[MAX_TILES];
__device__ int d_count[N_EXP];
__device__ int d_cursor[N_EXP];
__device__ int d_off[N_EXP];
__device__ int d_fix_count;
__device__ int d_fix_rows[B_ROWS];

// ---------------- baseline-PTX helpers ----------------
__device__ __forceinline__ uint32_t smem_to_u32(const void* p) {
    uint32_t a;
    asm("{ .reg .u64 t; cvta.to.shared.u64 t, %1; cvt.u32.u64 %0, t; }" : "=r"(a) : "l"(p));
    return a;
}
#define CP_ASYNC16(dst, src) \
    asm volatile("cp.async.cg.shared.global [%0], [%1], 16;" :: "r"(dst), "l"(src))
#define CP_COMMIT() asm volatile("cp.async.commit_group;" ::: "memory")
#define CP_WAIT3()  asm volatile("cp.async.wait_group 3;" ::: "memory")

#define LDSM_X4(r0, r1, r2, r3, addr) \
    asm volatile("ldmatrix.sync.aligned.m8n8.x4.shared.b16 {%0,%1,%2,%3}, [%4];" \
        : "=r"(r0), "=r"(r1), "=r"(r2), "=r"(r3) : "r"(addr))

#define MMA_F16(d, a, b) \
    asm volatile("mma.sync.aligned.m16n8k16.row.col.f32.f16.f16.f32 " \
        "{%0,%1,%2,%3}, {%4,%5,%6,%7}, {%8,%9}, {%0,%1,%2,%3};" \
        : "+f"((d)[0]), "+f"((d)[1]), "+f"((d)[2]), "+f"((d)[3]) \
        : "r"((a)[0]), "r"((a)[1]), "r"((a)[2]), "r"((a)[3]), "r"((b)[0]), "r"((b)[1]))

__device__ __forceinline__ unsigned pack2(float a, float b) {
    const unsigned ha = (unsigned)__half_as_ushort(__float2half_rn(a));
    const unsigned hb = (unsigned)__half_as_ushort(__float2half_rn(b));
    return ha | (hb << 16);
}

// ---------------- conversions ----------------
__global__ void conv_f2h_kernel(const float* __restrict__ in, uint2* __restrict__ out)
{
    const size_t i = (size_t)blockIdx.x * 256 + threadIdx.x;
    const float4 v = reinterpret_cast<const float4*>(in)[i];
    out[i] = make_uint2(pack2(v.x, v.y), pack2(v.z, v.w));
}

// W [K,N] fp32 -> out [N][K] fp16 (transpose); grid.z = expert
__global__ void conv_w_kernel(const float* __restrict__ W, unsigned* __restrict__ out,
                              int K, int N)
{
    __shared__ float t[64][33];
    const int k0 = blockIdx.x * 64, n0 = blockIdx.y * 32;
    W   += (size_t)blockIdx.z * K * N;
    out += (size_t)blockIdx.z * N * (K / 2);
    for (int r = threadIdx.y; r < 64; r += 8)
        t[r][threadIdx.x] = W[(size_t)(k0 + r) * N + n0 + threadIdx.x];
    __syncthreads();
    for (int r = threadIdx.y; r < 32; r += 8)
        out[(size_t)(n0 + r) * (K / 2) + k0 / 2 + threadIdx.x] =
            pack2(t[2 * threadIdx.x][r], t[2 * threadIdx.x + 1][r]);
}

// fused conversion of all four stage-1 weights into Wcat [3584][1024] fp16
__global__ void conv_wcat_kernel(const float* __restrict__ Wc1, const float* __restrict__ Wr1,
                                 const float* __restrict__ Wa, const float* __restrict__ Wo1,
                                 unsigned* __restrict__ out)
{
    __shared__ float t[64][33];
    const int k0 = blockIdx.x * 64;
    const int nc0 = blockIdx.y * 32;
    const float* W; int N; int nl;
    if (nc0 < 1024)      { W = Wc1; N = 1024; nl = nc0; }
    else if (nc0 < 2048) { W = Wr1; N = 1024; nl = nc0 - 1024; }
    else if (nc0 < 3072) { W = Wa;  N = 1024; nl = nc0 - 2048; }
    else                 { W = Wo1; N = 512;  nl = nc0 - 3072; }
    for (int r = threadIdx.y; r < 64; r += 8)
        t[r][threadIdx.x] = W[(size_t)(k0 + r) * N + nl + threadIdx.x];
    __syncthreads();
    for (int r = threadIdx.y; r < 32; r += 8)
        out[(size_t)(nc0 + r) * KU + k0 / 2 + threadIdx.x] =
            pack2(t[2 * threadIdx.x][r], t[2 * threadIdx.x + 1][r]);
}

// combined init: perm, counts, tile map, fix counter, bias concat
__global__ void init_kernel(const float* bc1, const float* br1,
                            const float* ba, const float* bo1, float* bcat)
{
    const int i = blockIdx.x * blockDim.x + threadIdx.x;
    if (i < MAX_SLOTS) d_perm[i] = -1;
    if (i < N_EXP) { d_count[i] = 0; d_cursor[i] = 0; d_off[i] = 0; }
    if (i < MAX_TILES) d_tile_expert[i] = -1;
    if (i == 0) d_fix_count = 0;
    if (i < 1024)      bcat[i] = bc1[i];
    else if (i < 2048) bcat[i] = br1[i - 1024];
    else if (i < 3072) bcat[i] = ba[i - 2048];
    else if (i < 3584) bcat[i] = bo1[i - 3072];
}

// ---------------- HMMA GEMM with fused gather / depth epilogue ----------------
// 256 threads / 8 warps (warp 32x64), tile 128x128, BK=32, 5-stage cp.async ring
// mode: 0 -> fp32 C, 1 -> fp16-packed C, 2 -> depth-fuse (relu(acc+b)·We3 atomically into out)
// gatherA: A row index via d_perm (clamped to 0)
#define STAGE_B   20480
#define GSMEM_SZ  (STAGE_B * NSTAGE)      // 102400

__global__ __launch_bounds__(256, 2)
void gemm_hmma(const __half* __restrict__ A,
               const __half* __restrict__ Bw,
               const float* __restrict__ biasBase,
               void* __restrict__ Cv, int ldc, int lda,
               int useExpert, long long wStride, int biasStride,
               int mode, int gatherA,
               const float* __restrict__ We3)
{
    extern __shared__ __align__(128) unsigned char smem[];
    const int tileN = blockIdx.x, tileM = blockIdx.y;
    int e = 0;
    if (useExpert) { e = d_tile_expert[tileM]; if (e < 0) return; }

    const float* bias = biasBase + (size_t)e * biasStride;
    const __half* Bp = Bw + (size_t)e * wStride + (size_t)tileN * 128 * KDIM;

    const uint32_t sbase = smem_to_u32(smem);
    const int tid = threadIdx.x, wid = tid >> 5, lane = tid & 31;
    const int wm = wid >> 1, wn = wid & 1;
    const int lrow = lane & 15, lcol = lane >> 4;

    const int r0c = tid >> 2, s0c = tid & 3;
    const int r1c = 64 + (tid >> 2), s1c = tid & 3;

    // per-thread A row pointers (optionally through perm)
    int row0 = tileM * 128 + r0c, row1 = tileM * 128 + r1c;
    if (gatherA) {
        const int p0 = d_perm[row0]; row0 = (p0 < 0) ? 0 : p0;
        const int p1 = d_perm[row1]; row1 = (p1 < 0) ? 0 : p1;
    }
    const __half* A0 = A + (size_t)row0 * lda;
    const __half* A1 = A + (size_t)row1 * lda;

    auto issue = [&](int kt, int stage) {
        const uint32_t base = sbase + stage * STAGE_B;
        const int k0 = kt * 32;
        CP_ASYNC16(base + r0c * 80 + s0c * 16,         A0 + k0 + s0c * 8);
        CP_ASYNC16(base + r1c * 80 + s1c * 16,         A1 + k0 + s1c * 8);
        CP_ASYNC16(base + 10240 + r0c * 80 + s0c * 16, Bp + (size_t)r0c * KDIM + k0 + s0c * 8);
        CP_ASYNC16(base + 10240 + r1c * 80 + s1c * 16, Bp + (size_t)r1c * KDIM + k0 + s1c * 8);
    };

    float acc[2][8][4] = {};

    issue(0, 0); CP_COMMIT();
    issue(1, 1); CP_COMMIT();
    issue(2, 2); CP_COMMIT();
    issue(3, 3); CP_COMMIT();

    int sc = 0, si = 4;
    for (int kt = 0; kt < KITERS; kt++) {
        CP_WAIT3();
        __syncthreads();
        if (kt + 4 < KITERS) issue(kt + 4, si);
        CP_COMMIT();

        const uint32_t ab = sbase + sc * STAGE_B;
        const uint32_t bb = ab + 10240;
        #pragma unroll
        for (int kk = 0; kk < 2; kk++) {
            uint32_t a[2][4];
            #pragma unroll
            for (int i = 0; i < 2; i++) {
                const uint32_t addr = ab + (wm * 32 + i * 16 + lrow) * 80 + (kk * 16 + lcol * 8) * 2;
                LDSM_X4(a[i][0], a[i][1], a[i][2], a[i][3], addr);
            }
            uint32_t b[8][2];
            #pragma unroll
            for (int j4 = 0; j4 < 4; j4++) {
                uint32_t q0, q1, q2, q3;
                const uint32_t addr = bb + (wn * 64 + j4 * 16 + lrow) * 80 + (kk * 16 + lcol * 8) * 2;
                LDSM_X4(q0, q1, q2, q3, addr);
                b[2 * j4][0] = q0;     b[2 * j4][1] = q2;
                b[2 * j4 + 1][0] = q1; b[2 * j4 + 1][1] = q3;
            }
            #pragma unroll
            for (int i = 0; i < 2; i++)
                #pragma unroll
                for (int j = 0; j < 8; j++)
                    MMA_F16(acc[i][j], a[i], b[j]);
        }
        sc = (sc + 1 == NSTAGE) ? 0 : sc + 1;
        si = (si + 1 == NSTAGE) ? 0 : si + 1;
    }

    const int rbase = tileM * 128 + wm * 32 + (lane >> 2);
    const int cbase = tileN * 128 + wn * 64 + (lane & 3) * 2;

    if (mode == 2) {
        // depth-fuse epilogue: s[rp][t] = sum over this thread's cols of relu(v)*We3[col][t]
        const float* w3 = We3 + (size_t)e * D_DIM * 3;
        float s[4][3] = {};
        #pragma unroll
        for (int j = 0; j < 8; j++) {
            const int col = cbase + j * 8;
            const float2 bz = *reinterpret_cast<const float2*>(bias + col);
            const float w00 = w3[col * 3 + 0], w01 = w3[col * 3 + 1], w02 = w3[col * 3 + 2];
            const float w10 = w3[col * 3 + 3], w11 = w3[col * 3 + 4], w12 = w3[col * 3 + 5];
            #pragma unroll
            for (int i = 0; i < 2; i++) {
                const float v0 = fmaxf(acc[i][j][0] + bz.x, 0.f);
                const float v1 = fmaxf(acc[i][j][1] + bz.y, 0.f);
                const float v2 = fmaxf(acc[i][j][2] + bz.x, 0.f);
                const float v3 = fmaxf(acc[i][j][3] + bz.y, 0.f);
                s[i * 2 + 0][0] += v0 * w00 + v1 * w10;
                s[i * 2 + 0][1] += v0 * w01 + v1 * w11;
                s[i * 2 + 0][2] += v0 * w02 + v1 * w12;
                s[i * 2 + 1][0] += v2 * w00 + v3 * w10;
                s[i * 2 + 1][1] += v2 * w01 + v3 * w11;
                s[i * 2 + 1][2] += v2 * w02 + v3 * w12;
            }
        }
        // quad reduction over (lane&3)
        #pragma unroll
        for (int off = 1; off <= 2; off <<= 1)
            #pragma unroll
            for (int rp = 0; rp < 4; rp++)
                #pragma unroll
                for (int t = 0; t < 3; t++)
                    s[rp][t] += __shfl_xor_sync(0xffffffffu, s[rp][t], off);
        if ((lane & 3) == 0) {
            float* out = (float*)Cv;
            #pragma unroll
            for (int rp = 0; rp < 4; rp++) {
                static const int roff[4] = {0, 8, 16, 24};
                const int slot = rbase + roff[rp];
                const int p = d_perm[slot];
                if (p >= 0) {
                    atomicAdd(&out[(size_t)p * 24 + 21], s[rp][0]);
                    atomicAdd(&out[(size_t)p * 24 + 22], s[rp][1]);
                    atomicAdd(&out[(size_t)p * 24 + 23], s[rp][2]);
                }
            }
        }
    } else if (mode == 1) {
        unsigned* C16 = (unsigned*)Cv;
        const int ldu = ldc >> 1;
        #pragma unroll
        for (int j = 0; j < 8; j++) {
            const int col = cbase + j * 8;
            const float2 bz = *reinterpret_cast<const float2*>(bias + col);
            #pragma unroll
            for (int i = 0; i < 2; i++) {
                const int ra = rbase + i * 16;
                C16[(size_t)ra * ldu + (col >> 1)] =
                    pack2(fmaxf(acc[i][j][0] + bz.x, 0.f), fmaxf(acc[i][j][1] + bz.y, 0.f));
                C16[(size_t)(ra + 8) * ldu + (col >> 1)] =
                    pack2(fmaxf(acc[i][j][2] + bz.x, 0.f), fmaxf(acc[i][j][3] + bz.y, 0.f));
            }
        }
    } else {
        float* C = (float*)Cv;
        #pragma unroll
        for (int j = 0; j < 8; j++) {
            const int col = cbase + j * 8;
            const float2 bz = *reinterpret_cast<const float2*>(bias + col);
            #pragma unroll
            for (int i = 0; i < 2; i++) {
                const int ra = rbase + i * 16;
                float2 v0, v1;
                v0.x = fmaxf(acc[i][j][0] + bz.x, 0.f);
                v0.y = fmaxf(acc[i][j][1] + bz.y, 0.f);
                v1.x = fmaxf(acc[i][j][2] + bz.x, 0.f);
                v1.y = fmaxf(acc[i][j][3] + bz.y, 0.f);
                *reinterpret_cast<float2*>(C + (size_t)ra * ldc + col) = v0;
                *reinterpret_cast<float2*>(C + (size_t)(ra + 8) * ldc + col) = v1;
            }
        }
    }
}

// ---------------- fused head (fp16 inputs) + expert count + depth-bias seed ----------------
__global__ void head_kernel(const __half* __restrict__ HBh,
                            const float* __restrict__ Wc2, const float* __restrict__ bc2,
                            const float* __restrict__ Wo2, const float* __restrict__ bo2,
                            const float* __restrict__ Wr2, const float* __restrict__ br2,
                            const float* __restrict__ be3,
                            float* __restrict__ out)
{
    const int row = blockIdx.x * blockDim.y + threadIdx.y;
    if (row >= B_ROWS) return;
    const int lane = threadIdx.x;
    const __half2* h2 = reinterpret_cast<const __half2*>(HBh + (size_t)row * NCAT);

    float a[7] = {0,0,0,0,0,0,0};
    for (int k2 = lane; k2 < 512; k2 += 32) {
        const float2 hv = __half22float2(h2[k2]);
        const float* w = Wc2 + (2 * k2) * 7;
        #pragma unroll
        for (int c = 0; c < 7; c++) a[c] += hv.x * w[c] + hv.y * w[7 + c];
    }
    float o[6] = {0,0,0,0,0,0};
    for (int k2 = lane; k2 < 256; k2 += 32) {
        const float2 hv = __half22float2(h2[1536 + k2]);
        const float* w = Wo2 + (2 * k2) * 6;
        #pragma unroll
        for (int c = 0; c < 6; c++) o[c] += hv.x * w[c] + hv.y * w[6 + c];
    }
    float r = 0.f;
    for (int k2 = lane; k2 < 512; k2 += 32) {
        const float2 hv = __half22float2(h2[512 + k2]);
        r += hv.x * Wr2[2 * k2] + hv.y * Wr2[2 * k2 + 1];
    }

    #pragma unroll
    for (int off = 16; off; off >>= 1) {
        #pragma unroll
        for (int c = 0; c < 7; c++) a[c] += __shfl_xor_sync(0xffffffffu, a[c], off);
        #pragma unroll
        for (int c = 0; c < 6; c++) o[c] += __shfl_xor_sync(0xffffffffu, o[c], off);
        r += __shfl_xor_sync(0xffffffffu, r, off);
    }
    if (lane == 0) {
        float sl[7];
        #pragma unroll
        for (int c = 0; c < 7; c++) sl[c] = a[c] + bc2[c];
        float mx = sl[0];
        #pragma unroll
        for (int c = 1; c < 7; c++) mx = fmaxf(mx, sl[c]);
        float ex[7], s = 0.f;
        #pragma unroll
        for (int c = 0; c < 7; c++) { ex[c] = expf(sl[c] - mx); s += ex[c]; }
        const float inv = 1.f / s;

        float expected = 0.f;
        int idx = 0; float best = sl[0], best2 = -1e30f;
        float* orow = out + (size_t)row * 24;
        #pragma unroll
        for (int c = 0; c < 7; c++) {
            const float p = ex[c] * inv;
            expected = fmaf(p, (float)c * (1.0f / 6.0f), expected);
            orow[c] = sl[c];
            orow[14 + c] = p;
            if (c > 0) {
                if (sl[c] > best) { best2 = best; best = sl[c]; idx = c; }
                else if (sl[c] > best2) best2 = sl[c];
            }
        }
        #pragma unroll
        for (int c = 0; c < 6; c++) orow[7 + c] = o[c] + bo2[c];
        const float resid = 0.35f * tanhf(r + br2[0]);
        orow[13] = fminf(fmaxf(expected + resid, 0.f), 1.f);
        // seed depth logits with bias of the chosen expert (gemm3 atomically adds partial dots)
        orow[21] = be3[idx * 3 + 0];
        orow[22] = be3[idx * 3 + 1];
        orow[23] = be3[idx * 3 + 2];
        d_size_idx[row] = idx;
        atomicAdd(&d_count[idx], 1);
        if (best - best2 < 4e-3f) {
            int p = atomicAdd(&d_fix_count, 1);
            if (p < B_ROWS) d_fix_rows[p] = row;
        }
    }
}

// exact fp32 argmax recompute for near-tie rows (adjusts counts + depth bias seed)
__global__ void fix_kernel(const float* __restrict__ x,
                           const float* __restrict__ Wc1, const float* __restrict__ bc1,
                           const float* __restrict__ Wc2, const float* __restrict__ bc2,
                           const float* __restrict__ be3,
                           float* __restrict__ out)
{
    __shared__ float xr[D_DIM];
    __shared__ float h[D_DIM];
    __shared__ float lg[8];
    int n = d_fix_count; if (n > B_ROWS) n = B_ROWS;
    for (int i = blockIdx.x; i < n; i += gridDim.x) {
        const int row = d_fix_rows[i];
        for (int k = threadIdx.x; k < D_DIM; k += 256) xr[k] = x[(size_t)row * D_DIM + k];
        __syncthreads();
        for (int j = threadIdx.x; j < D_DIM; j += 256) {
            float s = bc1[j];
            for (int k = 0; k < D_DIM; k++) s = fmaf(xr[k], Wc1[(size_t)k * D_DIM + j], s);
            h[j] = fmaxf(s, 0.f);
        }
        __syncthreads();
        const int w = threadIdx.x >> 5, l = threadIdx.x & 31;
        if (w < 7) {
            float s = 0.f;
            for (int k = l; k < D_DIM; k += 32) s = fmaf(h[k], Wc2[k * 7 + w], s);
            #pragma unroll
            for (int off = 16; off; off >>= 1) s += __shfl_xor_sync(0xffffffffu, s, off);
            if (!l) lg[w] = s + bc2[w];
        }
        __syncthreads();
        if (threadIdx.x == 0) {
            int idx = 0; float best = lg[0];
            #pragma unroll
            for (int c = 1; c < 7; c++) if (lg[c] > best) { best = lg[c]; idx = c; }
            const int old = d_size_idx[row];
            if (idx != old) {
                atomicSub(&d_count[old], 1);
                atomicAdd(&d_count[idx], 1);
                d_size_idx[row] = idx;
                float* orow = out + (size_t)row * 24;
                orow[21] = be3[idx * 3 + 0];
                orow[22] = be3[idx * 3 + 1];
                orow[23] = be3[idx * 3 + 2];
            }
        }
        __syncthreads();
    }
}

// ---------------- routing scan + scatter ----------------
__global__ void scan_kernel()
{
    int off = 0;
    for (int e = 0; e < N_EXP; e++) {
        d_off[e] = off;
        const int tiles = (d_count[e] + 127) >> 7;
        const int base = off >> 7;
        for (int t = 0; t < tiles; t++) d_tile_expert[base + t] = e;
        off += tiles << 7;
    }
}
__global__ void scatter_kernel()
{
    const int r = blockIdx.x * blockDim.x + threadIdx.x;
    if (r < B_ROWS) {
        const int e = d_size_idx[r];
        const int pos = d_off[e] + atomicAdd(&d_cursor[e], 1);
        d_perm[pos] = r;
    }
}

// ---------------- launch ----------------
extern "C" void kernel_launch(void* const* d_in, const int* in_sizes, int n_in,
                              void* d_out, int out_size)
{
    const float* x   = (const float*)d_in[0];
    const float* Wc1 = (const float*)d_in[1];
    const float* bc1 = (const float*)d_in[2];
    const float* Wc2 = (const float*)d_in[3];
    const float* bc2 = (const float*)d_in[4];
    const float* Wo1 = (const float*)d_in[5];
    const float* bo1 = (const float*)d_in[6];
    const float* Wo2 = (const float*)d_in[7];
    const float* bo2 = (const float*)d_in[8];
    const float* Wr1 = (const float*)d_in[9];
    const float* br1 = (const float*)d_in[10];
    const float* Wr2 = (const float*)d_in[11];
    const float* br2 = (const float*)d_in[12];
    const float* Wa  = (const float*)d_in[13];
    const float* ba  = (const float*)d_in[14];
    const float* We1 = (const float*)d_in[15];
    const float* be1 = (const float*)d_in[16];
    const float* We2 = (const float*)d_in[17];
    const float* be2 = (const float*)d_in[18];
    const float* We3 = (const float*)d_in[19];
    const float* be3 = (const float*)d_in[20];
    float* out = (float*)d_out;

    float* buf = nullptr;
    cudaGetSymbolAddress((void**)&buf, g_buf);
    __half*   HBh  = (__half*)(buf + OFF_HB);
    unsigned* X2   = (unsigned*)(buf + OFF_X2);
    unsigned* H12  = (unsigned*)(buf + OFF_H12);
    unsigned* Wcat = (unsigned*)(buf + OFF_WCAT);
    unsigned* W2e1 = (unsigned*)(buf + OFF_WE1);
    unsigned* W2e2 = (unsigned*)(buf + OFF_WE2);
    float*    bcat = buf + OFF_BCAT;

    cudaFuncSetAttribute(gemm_hmma, cudaFuncAttributeMaxDynamicSharedMemorySize, GSMEM_SZ);

    // conversions + init (plain fp16)
    conv_f2h_kernel<<<B_ROWS, 256>>>(x, (uint2*)X2);
    conv_wcat_kernel<<<dim3(16, 112), dim3(32, 8)>>>(Wc1, Wr1, Wa, Wo1, Wcat);
    conv_w_kernel<<<dim3(16, 32, N_EXP), dim3(32, 8)>>>(We1, W2e1, D_DIM, D_DIM);
    conv_w_kernel<<<dim3(16, 32, N_EXP), dim3(32, 8)>>>(We2, W2e2, D_DIM, D_DIM);
    init_kernel<<<(MAX_SLOTS + 255) / 256, 256>>>(bc1, br1, ba, bo1, bcat);

    // fused stage-1 GEMM: HB(fp16) = relu(X @ Wcat^T + bcat)
    gemm_hmma<<<dim3(NCAT / 128, B_ROWS / 128), 256, GSMEM_SZ>>>(
        (const __half*)X2, (const __half*)Wcat, bcat, HBh, NCAT, KDIM,
        0, 0, 0, 1, 0, nullptr);

    // heads (+count +depth-bias seed) + near-tie fp32 fixup + routing tables
    head_kernel<<<B_ROWS / 8, dim3(32, 8)>>>(HBh, Wc2, bc2, Wo2, bo2, Wr2, br2, be3, out);
    fix_kernel<<<64, 256>>>(x, Wc1, bc1, Wc2, bc2, be3, out);
    scan_kernel<<<1, 1>>>();
    scatter_kernel<<<(B_ROWS + 255) / 256, 256>>>();

    // expert MLP: gemm2 gathers A rows through perm from HB's Df columns;
    // gemm3 fuses relu + depth projection (atomicAdd into out cols 21..23)
    gemm_hmma<<<dim3(8, MAX_TILES), 256, GSMEM_SZ>>>(
        (const __half*)(HBh + 2048), (const __half*)W2e1, be1, H12, D_DIM, NCAT,
        1, (long long)D_DIM * KDIM, D_DIM, 1, 1, nullptr);
    gemm_hmma<<<dim3(8, MAX_TILES), 256, GSMEM_SZ>>>(
        (const __half*)H12, (const __half*)W2e2, be2, out, 24, KDIM,
        1, (long long)D_DIM * KDIM, D_DIM, 2, 0, We3);
}

// round 12
// speedup vs baseline: 1.1364x; 1.0450x over previous
#include <cuda_runtime.h>
#include <cuda_fp16.h>
#include <math.h>
#include <stdint.h>

// ---------------- constants ----------------
#define B_ROWS   16384
#define D_DIM    1024
#define KDIM     1024           // fp16 K
#define KU       512
#define NCAT     3584           // 1024(Wc1)+1024(Wr1)+1024(Wa)+512(Wo1)
#define ORD_H    512
#define N_EXP    7
#define MAX_TILES 136
#define MAX_SLOTS (MAX_TILES*128)
#define KITERS   32             // KDIM / 32
#define NSTAGE   5

// ---------------- scratch (float units) ----------------
#define OFF_DFH   0LL                      // Df fp16 [16384][1024]
#define OFF_X2    8388608LL                // X fp16 [16384][1024]
#define OFF_H12   16777216LL               // H1 fp16 [17408][1024]
#define OFF_WCAT  25690112LL               // Wcat fp16 [3584][1024]
#define OFF_WE1   27525120LL               // We1 fp16 [7][1024][1024]
#define OFF_WE2   31195136LL
#define OFF_BCAT  34865152LL               // bcat fp32 [3584]
#define OFF_LG    34868736LL               // Lg fp32 [16384][16]
#define TOTAL_F   35130880LL

__device__ __align__(1024) float g_buf[TOTAL_F];

__device__ int d_size_idx[B_ROWS];
__device__ int d_perm[MAX_SLOTS];
__device__ int d_tile_expert[MAX_TILES];
__device__ int d_count[N_EXP];
__device__ int d_cursor[N_EXP];
__device__ int d_off[N_EXP];
__device__ int d_fix_count;
__device__ int d_fix_rows[B_ROWS];

// ---------------- baseline-PTX helpers ----------------
__device__ __forceinline__ uint32_t smem_to_u32(const void* p) {
    uint32_t a;
    asm("{ .reg .u64 t; cvta.to.shared.u64 t, %1; cvt.u32.u64 %0, t; }" : "=r"(a) : "l"(p));
    return a;
}
#define CP_ASYNC16(dst, src) \
    asm volatile("cp.async.cg.shared.global [%0], [%1], 16;" :: "r"(dst), "l"(src))
#define CP_COMMIT() asm volatile("cp.async.commit_group;" ::: "memory")
#define CP_WAIT3()  asm volatile("cp.async.wait_group 3;" ::: "memory")

#define LDSM_X4(r0, r1, r2, r3, addr) \
    asm volatile("ldmatrix.sync.aligned.m8n8.x4.shared.b16 {%0,%1,%2,%3}, [%4];" \
        : "=r"(r0), "=r"(r1), "=r"(r2), "=r"(r3) : "r"(addr))

#define MMA_F16(d, a, b) \
    asm volatile("mma.sync.aligned.m16n8k16.row.col.f32.f16.f16.f32 " \
        "{%0,%1,%2,%3}, {%4,%5,%6,%7}, {%8,%9}, {%0,%1,%2,%3};" \
        : "+f"((d)[0]), "+f"((d)[1]), "+f"((d)[2]), "+f"((d)[3]) \
        : "r"((a)[0]), "r"((a)[1]), "r"((a)[2]), "r"((a)[3]), "r"((b)[0]), "r"((b)[1]))

__device__ __forceinline__ unsigned pack2(float a, float b) {
    const unsigned ha = (unsigned)__half_as_ushort(__float2half_rn(a));
    const unsigned hb = (unsigned)__half_as_ushort(__float2half_rn(b));
    return ha | (hb << 16);
}

// ---------------- conversions ----------------
__global__ void conv_f2h_kernel(const float* __restrict__ in, uint2* __restrict__ out)
{
    const size_t i = (size_t)blockIdx.x * 256 + threadIdx.x;
    const float4 v = reinterpret_cast<const float4*>(in)[i];
    out[i] = make_uint2(pack2(v.x, v.y), pack2(v.z, v.w));
}

// W [K,N] fp32 -> out [N][K] fp16 (transpose); grid.z = expert
__global__ void conv_w_kernel(const float* __restrict__ W, unsigned* __restrict__ out,
                              int K, int N)
{
    __shared__ float t[64][33];
    const int k0 = blockIdx.x * 64, n0 = blockIdx.y * 32;
    W   += (size_t)blockIdx.z * K * N;
    out += (size_t)blockIdx.z * N * (K / 2);
    for (int r = threadIdx.y; r < 64; r += 8)
        t[r][threadIdx.x] = W[(size_t)(k0 + r) * N + n0 + threadIdx.x];
    __syncthreads();
    for (int r = threadIdx.y; r < 32; r += 8)
        out[(size_t)(n0 + r) * (K / 2) + k0 / 2 + threadIdx.x] =
            pack2(t[2 * threadIdx.x][r], t[2 * threadIdx.x + 1][r]);
}

// fused conversion of all four stage-1 weights into Wcat [3584][1024] fp16
__global__ void conv_wcat_kernel(const float* __restrict__ Wc1, const float* __restrict__ Wr1,
                                 const float* __restrict__ Wa, const float* __restrict__ Wo1,
                                 unsigned* __restrict__ out)
{
    __shared__ float t[64][33];
    const int k0 = blockIdx.x * 64;
    const int nc0 = blockIdx.y * 32;
    const float* W; int N; int nl;
    if (nc0 < 1024)      { W = Wc1; N = 1024; nl = nc0; }
    else if (nc0 < 2048) { W = Wr1; N = 1024; nl = nc0 - 1024; }
    else if (nc0 < 3072) { W = Wa;  N = 1024; nl = nc0 - 2048; }
    else                 { W = Wo1; N = 512;  nl = nc0 - 3072; }
    for (int r = threadIdx.y; r < 64; r += 8)
        t[r][threadIdx.x] = W[(size_t)(k0 + r) * N + nl + threadIdx.x];
    __syncthreads();
    for (int r = threadIdx.y; r < 32; r += 8)
        out[(size_t)(nc0 + r) * KU + k0 / 2 + threadIdx.x] =
            pack2(t[2 * threadIdx.x][r], t[2 * threadIdx.x + 1][r]);
}

// combined init: perm, counts, tile map, fix counter, bias concat, Lg zero
__global__ void init_kernel(const float* bc1, const float* br1,
                            const float* ba, const float* bo1,
                            float* bcat, float* Lg)
{
    const int i = blockIdx.x * blockDim.x + threadIdx.x;
    if (i < B_ROWS * 16) Lg[i] = 0.f;
    if (i < MAX_SLOTS) d_perm[i] = -1;
    if (i < N_EXP) { d_count[i] = 0; d_cursor[i] = 0; d_off[i] = 0; }
    if (i < MAX_TILES) d_tile_expert[i] = -1;
    if (i == 0) d_fix_count = 0;
    if (i < 1024)      bcat[i] = bc1[i];
    else if (i < 2048) bcat[i] = br1[i - 1024];
    else if (i < 3072) bcat[i] = ba[i - 2048];
    else if (i < 3584) bcat[i] = bo1[i - 3072];
}

// ---------------- HMMA GEMM with fused epilogues ----------------
// 256 threads / 8 warps (warp 32x64), tile 128x128, BK=32, 5-stage cp.async ring
// mode: 1 -> fp16-packed C
//       2 -> depth-fuse (relu(acc+b)·We3 atomically into out cols 21..23)
//       3 -> stage-1 fused: head tiles -> Lg atomics, Df tiles -> fp16 store
// gatherA: A row index via d_perm (clamped to 0)
#define STAGE_B   20480
#define GSMEM_SZ  (STAGE_B * NSTAGE)      // 102400

__global__ __launch_bounds__(256, 2)
void gemm_hmma(const __half* __restrict__ A,
               const __half* __restrict__ Bw,
               const float* __restrict__ biasBase,
               void* __restrict__ Cv, int ldc, int lda,
               int useExpert, long long wStride, int biasStride,
               int mode, int gatherA,
               const float* __restrict__ We3,
               const float* __restrict__ Wc2,
               const float* __restrict__ Wr2,
               const float* __restrict__ Wo2,
               float* __restrict__ Lg)
{
    extern __shared__ __align__(128) unsigned char smem[];
    const int tileN = blockIdx.x, tileM = blockIdx.y;
    int e = 0;
    if (useExpert) { e = d_tile_expert[tileM]; if (e < 0) return; }

    const float* bias = biasBase + (size_t)e * biasStride;
    const __half* Bp = Bw + (size_t)e * wStride + (size_t)tileN * 128 * KDIM;

    const uint32_t sbase = smem_to_u32(smem);
    const int tid = threadIdx.x, wid = tid >> 5, lane = tid & 31;
    const int wm = wid >> 1, wn = wid & 1;
    const int lrow = lane & 15, lcol = lane >> 4;

    const int r0c = tid >> 2, s0c = tid & 3;
    const int r1c = 64 + (tid >> 2), s1c = tid & 3;

    int row0 = tileM * 128 + r0c, row1 = tileM * 128 + r1c;
    if (gatherA) {
        const int p0 = d_perm[row0]; row0 = (p0 < 0) ? 0 : p0;
        const int p1 = d_perm[row1]; row1 = (p1 < 0) ? 0 : p1;
    }
    const __half* A0 = A + (size_t)row0 * lda;
    const __half* A1 = A + (size_t)row1 * lda;

    auto issue = [&](int kt, int stage) {
        const uint32_t base = sbase + stage * STAGE_B;
        const int k0 = kt * 32;
        CP_ASYNC16(base + r0c * 80 + s0c * 16,         A0 + k0 + s0c * 8);
        CP_ASYNC16(base + r1c * 80 + s1c * 16,         A1 + k0 + s1c * 8);
        CP_ASYNC16(base + 10240 + r0c * 80 + s0c * 16, Bp + (size_t)r0c * KDIM + k0 + s0c * 8);
        CP_ASYNC16(base + 10240 + r1c * 80 + s1c * 16, Bp + (size_t)r1c * KDIM + k0 + s1c * 8);
    };

    float acc[2][8][4] = {};

    issue(0, 0); CP_COMMIT();
    issue(1, 1); CP_COMMIT();
    issue(2, 2); CP_COMMIT();
    issue(3, 3); CP_COMMIT();

    int sc = 0, si = 4;
    for (int kt = 0; kt < KITERS; kt++) {
        CP_WAIT3();
        __syncthreads();
        if (kt + 4 < KITERS) issue(kt + 4, si);
        CP_COMMIT();

        const uint32_t ab = sbase + sc * STAGE_B;
        const uint32_t bb = ab + 10240;
        #pragma unroll
        for (int kk = 0; kk < 2; kk++) {
            uint32_t a[2][4];
            #pragma unroll
            for (int i = 0; i < 2; i++) {
                const uint32_t addr = ab + (wm * 32 + i * 16 + lrow) * 80 + (kk * 16 + lcol * 8) * 2;
                LDSM_X4(a[i][0], a[i][1], a[i][2], a[i][3], addr);
            }
            uint32_t b[8][2];
            #pragma unroll
            for (int j4 = 0; j4 < 4; j4++) {
                uint32_t q0, q1, q2, q3;
                const uint32_t addr = bb + (wn * 64 + j4 * 16 + lrow) * 80 + (kk * 16 + lcol * 8) * 2;
                LDSM_X4(q0, q1, q2, q3, addr);
                b[2 * j4][0] = q0;     b[2 * j4][1] = q2;
                b[2 * j4 + 1][0] = q1; b[2 * j4 + 1][1] = q3;
            }
            #pragma unroll
            for (int i = 0; i < 2; i++)
                #pragma unroll
                for (int j = 0; j < 8; j++)
                    MMA_F16(acc[i][j], a[i], b[j]);
        }
        sc = (sc + 1 == NSTAGE) ? 0 : sc + 1;
        si = (si + 1 == NSTAGE) ? 0 : si + 1;
    }

    const int rbase = tileM * 128 + wm * 32 + (lane >> 2);
    const int cbase = tileN * 128 + wn * 64 + (lane & 3) * 2;
    static const int roff[4] = {0, 8, 16, 24};

    const bool df_store = (mode == 3) && (tileN >= 16 && tileN < 24);
    if (mode == 1 || df_store) {
        // fp16-packed store; for Df tiles the column base is rebased to 0
        unsigned* C16 = (unsigned*)Cv;
        const int ldu = ldc >> 1;
        const int creb = df_store ? 2048 : 0;
        #pragma unroll
        for (int j = 0; j < 8; j++) {
            const int col = cbase + j * 8;
            const float2 bz = *reinterpret_cast<const float2*>(bias + col);
            const int cl = col - creb;
            #pragma unroll
            for (int i = 0; i < 2; i++) {
                const int ra = rbase + i * 16;
                C16[(size_t)ra * ldu + (cl >> 1)] =
                    pack2(fmaxf(acc[i][j][0] + bz.x, 0.f), fmaxf(acc[i][j][1] + bz.y, 0.f));
                C16[(size_t)(ra + 8) * ldu + (cl >> 1)] =
                    pack2(fmaxf(acc[i][j][2] + bz.x, 0.f), fmaxf(acc[i][j][3] + bz.y, 0.f));
            }
        }
    } else if (mode == 3) {
        // head tiles: s[row][c] = sum_cols relu(v+b) * W2[colLocal][c]
        int nOut, lgoff, creg;
        const float* W2;
        if (tileN < 8)       { nOut = 7; W2 = Wc2; lgoff = 0; creg = 0; }
        else if (tileN < 16) { nOut = 1; W2 = Wr2; lgoff = 7; creg = 1024; }
        else                 { nOut = 6; W2 = Wo2; lgoff = 8; creg = 3072; }
        float s[4][7];
        #pragma unroll
        for (int rp = 0; rp < 4; rp++)
            #pragma unroll
            for (int c = 0; c < 7; c++) s[rp][c] = 0.f;
        #pragma unroll
        for (int j = 0; j < 8; j++) {
            const int col = cbase + j * 8;
            const float2 bz = *reinterpret_cast<const float2*>(bias + col);
            const int cl = col - creg;
            #pragma unroll
            for (int c = 0; c < 7; c++) {
                if (c < nOut) {
                    const float w0 = W2[(size_t)cl * nOut + c];
                    const float w1 = W2[(size_t)(cl + 1) * nOut + c];
                    #pragma unroll
                    for (int i = 0; i < 2; i++) {
                        const float v0 = fmaxf(acc[i][j][0] + bz.x, 0.f);
                        const float v1 = fmaxf(acc[i][j][1] + bz.y, 0.f);
                        const float v2 = fmaxf(acc[i][j][2] + bz.x, 0.f);
                        const float v3 = fmaxf(acc[i][j][3] + bz.y, 0.f);
                        s[i * 2 + 0][c] += v0 * w0 + v1 * w1;
                        s[i * 2 + 1][c] += v2 * w0 + v3 * w1;
                    }
                }
            }
        }
        #pragma unroll
        for (int off = 1; off <= 2; off <<= 1)
            #pragma unroll
            for (int rp = 0; rp < 4; rp++)
                #pragma unroll
                for (int c = 0; c < 7; c++)
                    s[rp][c] += __shfl_xor_sync(0xffffffffu, s[rp][c], off);
        if ((lane & 3) == 0) {
            #pragma unroll
            for (int rp = 0; rp < 4; rp++) {
                const int row = rbase + roff[rp];
                #pragma unroll
                for (int c = 0; c < 7; c++)
                    if (c < nOut) atomicAdd(&Lg[(size_t)row * 16 + lgoff + c], s[rp][c]);
            }
        }
    } else {
        // mode 2: depth-fuse epilogue
        const float* w3 = We3 + (size_t)e * D_DIM * 3;
        float s[4][3] = {};
        #pragma unroll
        for (int j = 0; j < 8; j++) {
            const int col = cbase + j * 8;
            const float2 bz = *reinterpret_cast<const float2*>(bias + col);
            const float w00 = w3[col * 3 + 0], w01 = w3[col * 3 + 1], w02 = w3[col * 3 + 2];
            const float w10 = w3[col * 3 + 3], w11 = w3[col * 3 + 4], w12 = w3[col * 3 + 5];
            #pragma unroll
            for (int i = 0; i < 2; i++) {
                const float v0 = fmaxf(acc[i][j][0] + bz.x, 0.f);
                const float v1 = fmaxf(acc[i][j][1] + bz.y, 0.f);
                const float v2 = fmaxf(acc[i][j][2] + bz.x, 0.f);
                const float v3 = fmaxf(acc[i][j][3] + bz.y, 0.f);
                s[i * 2 + 0][0] += v0 * w00 + v1 * w10;
                s[i * 2 + 0][1] += v0 * w01 + v1 * w11;
                s[i * 2 + 0][2] += v0 * w02 + v1 * w12;
                s[i * 2 + 1][0] += v2 * w00 + v3 * w10;
                s[i * 2 + 1][1] += v2 * w01 + v3 * w11;
                s[i * 2 + 1][2] += v2 * w02 + v3 * w12;
            }
        }
        #pragma unroll
        for (int off = 1; off <= 2; off <<= 1)
            #pragma unroll
            for (int rp = 0; rp < 4; rp++)
                #pragma unroll
                for (int t = 0; t < 3; t++)
                    s[rp][t] += __shfl_xor_sync(0xffffffffu, s[rp][t], off);
        if ((lane & 3) == 0) {
            float* out = (float*)Cv;
            #pragma unroll
            for (int rp = 0; rp < 4; rp++) {
                const int slot = rbase + roff[rp];
                const int p = d_perm[slot];
                if (p >= 0) {
                    atomicAdd(&out[(size_t)p * 24 + 21], s[rp][0]);
                    atomicAdd(&out[(size_t)p * 24 + 22], s[rp][1]);
                    atomicAdd(&out[(size_t)p * 24 + 23], s[rp][2]);
                }
            }
        }
    }
}

// ---------------- head finalize: softmax/argmax/reg + routing (1 thread/row) ----------------
__global__ void head2_kernel(const float* __restrict__ Lg,
                             const float* __restrict__ bc2, const float* __restrict__ bo2,
                             const float* __restrict__ br2, const float* __restrict__ be3,
                             float* __restrict__ out)
{
    const int row = blockIdx.x * blockDim.x + threadIdx.x;
    if (row >= B_ROWS) return;
    const float* lg = Lg + (size_t)row * 16;

    float sl[7];
    #pragma unroll
    for (int c = 0; c < 7; c++) sl[c] = lg[c] + bc2[c];
    float mx = sl[0];
    #pragma unroll
    for (int c = 1; c < 7; c++) mx = fmaxf(mx, sl[c]);
    float ex[7], ssum = 0.f;
    #pragma unroll
    for (int c = 0; c < 7; c++) { ex[c] = expf(sl[c] - mx); ssum += ex[c]; }
    const float inv = 1.f / ssum;

    float expected = 0.f;
    int idx = 0; float best = sl[0], best2 = -1e30f;
    float* orow = out + (size_t)row * 24;
    #pragma unroll
    for (int c = 0; c < 7; c++) {
        const float p = ex[c] * inv;
        expected = fmaf(p, (float)c * (1.0f / 6.0f), expected);
        orow[c] = sl[c];
        orow[14 + c] = p;
        if (c > 0) {
            if (sl[c] > best) { best2 = best; best = sl[c]; idx = c; }
            else if (sl[c] > best2) best2 = sl[c];
        }
    }
    #pragma unroll
    for (int c = 0; c < 6; c++) orow[7 + c] = lg[8 + c] + bo2[c];
    const float resid = 0.35f * tanhf(lg[7] + br2[0]);
    orow[13] = fminf(fmaxf(expected + resid, 0.f), 1.f);
    orow[21] = be3[idx * 3 + 0];
    orow[22] = be3[idx * 3 + 1];
    orow[23] = be3[idx * 3 + 2];
    d_size_idx[row] = idx;
    atomicAdd(&d_count[idx], 1);
    if (best - best2 < 4e-3f) {
        int p = atomicAdd(&d_fix_count, 1);
        if (p < B_ROWS) d_fix_rows[p] = row;
    }
}

// exact fp32 argmax recompute for near-tie rows (adjusts counts + depth bias seed)
__global__ void fix_kernel(const float* __restrict__ x,
                           const float* __restrict__ Wc1, const float* __restrict__ bc1,
                           const float* __restrict__ Wc2, const float* __restrict__ bc2,
                           const float* __restrict__ be3,
                           float* __restrict__ out)
{
    __shared__ float xr[D_DIM];
    __shared__ float h[D_DIM];
    __shared__ float lg[8];
    int n = d_fix_count; if (n > B_ROWS) n = B_ROWS;
    for (int i = blockIdx.x; i < n; i += gridDim.x) {
        const int row = d_fix_rows[i];
        for (int k = threadIdx.x; k < D_DIM; k += 256) xr[k] = x[(size_t)row * D_DIM + k];
        __syncthreads();
        for (int j = threadIdx.x; j < D_DIM; j += 256) {
            float s = bc1[j];
            for (int k = 0; k < D_DIM; k++) s = fmaf(xr[k], Wc1[(size_t)k * D_DIM + j], s);
            h[j] = fmaxf(s, 0.f);
        }
        __syncthreads();
        const int w = threadIdx.x >> 5, l = threadIdx.x & 31;
        if (w < 7) {
            float s = 0.f;
            for (int k = l; k < D_DIM; k += 32) s = fmaf(h[k], Wc2[k * 7 + w], s);
            #pragma unroll
            for (int off = 16; off; off >>= 1) s += __shfl_xor_sync(0xffffffffu, s, off);
            if (!l) lg[w] = s + bc2[w];
        }
        __syncthreads();
        if (threadIdx.x == 0) {
            int idx = 0; float best = lg[0];
            #pragma unroll
            for (int c = 1; c < 7; c++) if (lg[c] > best) { best = lg[c]; idx = c; }
            const int old = d_size_idx[row];
            if (idx != old) {
                atomicSub(&d_count[old], 1);
                atomicAdd(&d_count[idx], 1);
                d_size_idx[row] = idx;
                float* orow = out + (size_t)row * 24;
                orow[21] = be3[idx * 3 + 0];
                orow[22] = be3[idx * 3 + 1];
                orow[23] = be3[idx * 3 + 2];
            }
        }
        __syncthreads();
    }
}

// ---------------- routing scan + scatter ----------------
__global__ void scan_kernel()
{
    int off = 0;
    for (int e = 0; e < N_EXP; e++) {
        d_off[e] = off;
        const int tiles = (d_count[e] + 127) >> 7;
        const int base = off >> 7;
        for (int t = 0; t < tiles; t++) d_tile_expert[base + t] = e;
        off += tiles << 7;
    }
}
__global__ void scatter_kernel()
{
    const int r = blockIdx.x * blockDim.x + threadIdx.x;
    if (r < B_ROWS) {
        const int e = d_size_idx[r];
        const int pos = d_off[e] + atomicAdd(&d_cursor[e], 1);
        d_perm[pos] = r;
    }
}

// ---------------- launch ----------------
extern "C" void kernel_launch(void* const* d_in, const int* in_sizes, int n_in,
                              void* d_out, int out_size)
{
    const float* x   = (const float*)d_in[0];
    const float* Wc1 = (const float*)d_in[1];
    const float* bc1 = (const float*)d_in[2];
    const float* Wc2 = (const float*)d_in[3];
    const float* bc2 = (const float*)d_in[4];
    const float* Wo1 = (const float*)d_in[5];
    const float* bo1 = (const float*)d_in[6];
    const float* Wo2 = (const float*)d_in[7];
    const float* bo2 = (const float*)d_in[8];
    const float* Wr1 = (const float*)d_in[9];
    const float* br1 = (const float*)d_in[10];
    const float* Wr2 = (const float*)d_in[11];
    const float* br2 = (const float*)d_in[12];
    const float* Wa  = (const float*)d_in[13];
    const float* ba  = (const float*)d_in[14];
    const float* We1 = (const float*)d_in[15];
    const float* be1 = (const float*)d_in[16];
    const float* We2 = (const float*)d_in[17];
    const float* be2 = (const float*)d_in[18];
    const float* We3 = (const float*)d_in[19];
    const float* be3 = (const float*)d_in[20];
    float* out = (float*)d_out;

    float* buf = nullptr;
    cudaGetSymbolAddress((void**)&buf, g_buf);
    __half*   Dfh  = (__half*)(buf + OFF_DFH);
    unsigned* X2   = (unsigned*)(buf + OFF_X2);
    unsigned* H12  = (unsigned*)(buf + OFF_H12);
    unsigned* Wcat = (unsigned*)(buf + OFF_WCAT);
    unsigned* W2e1 = (unsigned*)(buf + OFF_WE1);
    unsigned* W2e2 = (unsigned*)(buf + OFF_WE2);
    float*    bcat = buf + OFF_BCAT;
    float*    Lg   = buf + OFF_LG;

    cudaFuncSetAttribute(gemm_hmma, cudaFuncAttributeMaxDynamicSharedMemorySize, GSMEM_SZ);

    // 1-3: conversions + init (gemm1 at launch #4 for ncu visibility)
    conv_f2h_kernel<<<B_ROWS, 256>>>(x, (uint2*)X2);
    conv_wcat_kernel<<<dim3(16, 112), dim3(32, 8)>>>(Wc1, Wr1, Wa, Wo1, Wcat);
    init_kernel<<<(B_ROWS * 16 + 255) / 256, 256>>>(bc1, br1, ba, bo1, bcat, Lg);

    // 4: fused stage-1 GEMM: head dots -> Lg (atomics), Df -> fp16 Dfh
    gemm_hmma<<<dim3(NCAT / 128, B_ROWS / 128), 256, GSMEM_SZ>>>(
        (const __half*)X2, (const __half*)Wcat, bcat, Dfh, D_DIM, KDIM,
        0, 0, 0, 3, 0, nullptr, Wc2, Wr2, Wo2, Lg);

    // 5-6: expert weight conversions (independent of gemm1)
    conv_w_kernel<<<dim3(16, 32, N_EXP), dim3(32, 8)>>>(We1, W2e1, D_DIM, D_DIM);
    conv_w_kernel<<<dim3(16, 32, N_EXP), dim3(32, 8)>>>(We2, W2e2, D_DIM, D_DIM);

    // 7-10: head finalize + near-tie fixup + routing tables
    head2_kernel<<<(B_ROWS + 255) / 256, 256>>>(Lg, bc2, bo2, br2, be3, out);
    fix_kernel<<<64, 256>>>(x, Wc1, bc1, Wc2, bc2, be3, out);
    scan_kernel<<<1, 1>>>();
    scatter_kernel<<<(B_ROWS + 255) / 256, 256>>>();

    // 11-12: expert MLP (gemm2 gathers rows from dense Dfh; gemm3 depth-fused)
    gemm_hmma<<<dim3(8, MAX_TILES), 256, GSMEM_SZ>>>(
        (const __half*)Dfh, (const __half*)W2e1, be1, H12, D_DIM, D_DIM,
        1, (long long)D_DIM * KDIM, D_DIM, 1, 1, nullptr, nullptr, nullptr, nullptr, nullptr);
    gemm_hmma<<<dim3(8, MAX_TILES), 256, GSMEM_SZ>>>(
        (const __half*)H12, (const __half*)W2e2, be2, out, 24, KDIM,
        1, (long long)D_DIM * KDIM, D_DIM, 2, 0, We3, nullptr, nullptr, nullptr, nullptr);
}